// round 6
// baseline (speedup 1.0000x reference)
#include <cuda_runtime.h>
#include <cuda_fp16.h>
#include <cstdint>

#define M_TOK 8192
#define KDIM  4096
#define NOUT  4096

#define BM 128
#define BN 128
#define BK 64
#define KT (KDIM / BK)   // 64 k-tiles
#define STAGES 3

// ---------------- scratch (no allocs allowed) ----------------
__device__ __align__(16) int8_t g_qx[(size_t)M_TOK * KDIM];   // 32 MB quantized activations
__device__ __align__(16) int8_t g_qw8[(size_t)NOUT * KDIM];   // 16 MB repacked weights
__device__ __align__(16) int8_t g_b8[NOUT];                   // repacked bias
__device__ unsigned g_absmax_bits;
__device__ unsigned g_qw_mode;   // 0=int8-native, 1=int32, 2=float32
__device__ unsigned g_b_mode;

// ---------------- kernel 0: reset ----------------
__global__ void k_reset() { g_absmax_bits = 0u; }

// ---------------- kernel 0b: detect delivery dtype of the int8 arrays ----------------
// (expected: int32 per the harness promotion rule; detector kept as cheap insurance)
__global__ void k_detect(const void* qw, const void* b) {
    int t = threadIdx.x;           // 256 threads, 1 block
    {
        int i32ok = 1, f32ok = 1;
#pragma unroll
        for (int s = 0; s < 4; ++s) {
            int idx = ((t * 4 + s) * 4099) & (4194304 - 1);
            unsigned w = ((const unsigned*)qw)[idx];
            i32ok &= ((int)w == (int)(signed char)(w & 0xffu)) ? 1 : 0;
            float f = __uint_as_float(w);
            f32ok &= (f == rintf(f) && fabsf(f) <= 256.0f) ? 1 : 0;
        }
        int ni = __syncthreads_count(i32ok);
        int nf = __syncthreads_count(f32ok);
        if (t == 0) g_qw_mode = (ni == 256) ? 1u : ((nf == 256) ? 2u : 0u);
    }
    {
        int i32ok = 1, f32ok = 1;
#pragma unroll
        for (int s = 0; s < 4; ++s) {
            int idx = t * 4 + s;   // full census of 1024 words
            unsigned w = ((const unsigned*)b)[idx];
            i32ok &= ((int)w == (int)(signed char)(w & 0xffu)) ? 1 : 0;
            float f = __uint_as_float(w);
            f32ok &= (f == rintf(f) && fabsf(f) <= 256.0f) ? 1 : 0;
        }
        int ni = __syncthreads_count(i32ok);
        int nf = __syncthreads_count(f32ok);
        if (t == 0) g_b_mode = (ni == 256) ? 1u : ((nf == 256) ? 2u : 0u);
    }
}

// ---------------- kernel 0c: repack weights/bias to tight int8 ----------------
__device__ __forceinline__ unsigned pack4(int a, int b, int c, int d) {
    return (unsigned)(a & 0xff) | ((unsigned)(b & 0xff) << 8) |
           ((unsigned)(c & 0xff) << 16) | ((unsigned)(d & 0xff) << 24);
}

__global__ void k_repack_qw(const void* qw) {
    unsigned mode = g_qw_mode;
    unsigned* dst = (unsigned*)g_qw8;
    int n4 = (NOUT * KDIM) / 4;   // 4194304 output words
    int idx = blockIdx.x * blockDim.x + threadIdx.x;
    int stride = gridDim.x * blockDim.x;
    for (int i = idx; i < n4; i += stride) {
        unsigned o;
        if (mode == 1u) {
            int4 r = ((const int4*)qw)[i];
            o = pack4(r.x, r.y, r.z, r.w);
        } else if (mode == 2u) {
            float4 r = ((const float4*)qw)[i];
            o = pack4(__float2int_rn(r.x), __float2int_rn(r.y),
                      __float2int_rn(r.z), __float2int_rn(r.w));
        } else {
            o = ((const unsigned*)qw)[i];
        }
        dst[i] = o;
    }
}

__global__ void k_repack_b(const void* b) {
    unsigned mode = g_b_mode;
    unsigned* dst = (unsigned*)g_b8;
    int i = threadIdx.x;
    if (i < NOUT / 4) {
        unsigned o;
        if (mode == 1u) {
            int4 r = ((const int4*)b)[i];
            o = pack4(r.x, r.y, r.z, r.w);
        } else if (mode == 2u) {
            float4 r = ((const float4*)b)[i];
            o = pack4(__float2int_rn(r.x), __float2int_rn(r.y),
                      __float2int_rn(r.z), __float2int_rn(r.w));
        } else {
            o = ((const unsigned*)b)[i];
        }
        dst[i] = o;
    }
}

// ---------------- kernel 1: absmax over f32 x ----------------
// abs-masked f32 bit patterns are u32-monotonic for non-negatives -> integer max.
__global__ void k_absmax(const uint4* __restrict__ xv, int n4) {
    unsigned m = 0u;
    int idx = blockIdx.x * blockDim.x + threadIdx.x;
    int stride = gridDim.x * blockDim.x;
    for (int i = idx; i < n4; i += stride) {
        uint4 v = xv[i];
        m = max(m, v.x & 0x7fffffffu);
        m = max(m, v.y & 0x7fffffffu);
        m = max(m, v.z & 0x7fffffffu);
        m = max(m, v.w & 0x7fffffffu);
    }
#pragma unroll
    for (int o = 16; o; o >>= 1) m = max(m, __shfl_xor_sync(0xffffffffu, m, o));
    __shared__ unsigned sm[32];
    int lane = threadIdx.x & 31, wid = threadIdx.x >> 5;
    if (lane == 0) sm[wid] = m;
    __syncthreads();
    if (wid == 0) {
        unsigned v = (lane < (int)(blockDim.x >> 5)) ? sm[lane] : 0u;
#pragma unroll
        for (int o = 16; o; o >>= 1) v = max(v, __shfl_xor_sync(0xffffffffu, v, o));
        if (lane == 0) atomicMax(&g_absmax_bits, v);   // bits of non-negative f32: order ok
    }
}

// ---------------- kernel 2: quantize f32 x -> int8 ----------------
// Correctly-rounded f/s via Markstein (r = rcp.rn): q == RN(f/s).
__device__ __forceinline__ int quant1(float f, float s, float r) {
    float q0 = f * r;
    float e  = fmaf(-s, q0, f);
    float q  = fmaf(r, e, q0);
    float qf = rintf(q);                       // round-half-even == jnp.round
    qf = fminf(fmaxf(qf, -128.0f), 127.0f);    // jnp.clip
    return (int)qf;
}

__global__ void k_quant(const float4* __restrict__ xv, int n4) {
    float amax = __uint_as_float(g_absmax_bits);
    float s = __fdiv_rn(amax, 127.0f);   // exact RN (matches jax x_scale)
    float r = __frcp_rn(s);
    int idx = blockIdx.x * blockDim.x + threadIdx.x;
    int stride = gridDim.x * blockDim.x;
    unsigned* qx1 = reinterpret_cast<unsigned*>(g_qx);
    for (int i = idx; i < n4; i += stride) {
        float4 v = xv[i];
        qx1[i] = pack4(quant1(v.x, s, r), quant1(v.y, s, r),
                       quant1(v.z, s, r), quant1(v.w, s, r));
    }
}

// ---------------- kernel 3: int8 GEMM + requant epilogue ----------------
__device__ __forceinline__ void cp_async16(uint32_t dst, const void* src) {
    asm volatile("cp.async.cg.shared.global [%0], [%1], 16;" :: "r"(dst), "l"(src));
}
__device__ __forceinline__ void cp_commit() { asm volatile("cp.async.commit_group;"); }
__device__ __forceinline__ void cp_wait1()  { asm volatile("cp.async.wait_group 1;"); }

__device__ __forceinline__ int swz(int row, int c) {
    return row * 64 + ((c ^ ((row >> 1) & 3)) << 4);
}

__device__ __forceinline__ void ldsm_x4(uint32_t& r0, uint32_t& r1, uint32_t& r2, uint32_t& r3, uint32_t addr) {
    asm volatile("ldmatrix.sync.aligned.m8n8.x4.shared.b16 {%0,%1,%2,%3}, [%4];"
                 : "=r"(r0), "=r"(r1), "=r"(r2), "=r"(r3) : "r"(addr));
}

__device__ __forceinline__ void mma_s8(int* c, const uint32_t* a, const uint32_t* b) {
    asm volatile(
        "mma.sync.aligned.m16n8k32.row.col.s32.s8.s8.s32 "
        "{%0,%1,%2,%3}, {%4,%5,%6,%7}, {%8,%9}, {%0,%1,%2,%3};"
        : "+r"(c[0]), "+r"(c[1]), "+r"(c[2]), "+r"(c[3])
        : "r"(a[0]), "r"(a[1]), "r"(a[2]), "r"(a[3]), "r"(b[0]), "r"(b[1]));
}

// Exact reference chain: y = clip(round(acc*alpha)+b) * ys; fp16(y); harness promotes
// fp16 -> float32, so we emit float(fp16(y)).
__device__ __forceinline__ float requant(int a, float bf, float alpha, float ys) {
    float v = rintf(__int2float_rn(a) * alpha) + bf;
    v = fminf(fmaxf(v, -128.0f), 127.0f) * ys;
    return __half2float(__float2half_rn(v));
}

__global__ __launch_bounds__(256) void k_gemm(
    const float* __restrict__ s0_p, const float* __restrict__ s1_p,
    float* __restrict__ out)
{
    __shared__ __align__(16) int8_t sA[STAGES][BM * BK];
    __shared__ __align__(16) int8_t sB[STAGES][BN * BK];

    const int tid  = threadIdx.x;
    const int lane = tid & 31, warp = tid >> 5;
    const int wm = warp & 1;
    const int wn = warp >> 1;
    const int bm = blockIdx.y * BM, bn = blockIdx.x * BN;

    const uint32_t sAu = (uint32_t)__cvta_generic_to_shared(&sA[0][0]);
    const uint32_t sBu = (uint32_t)__cvta_generic_to_shared(&sB[0][0]);

    const int8_t* Ag = g_qx  + (size_t)bm * KDIM;
    const int8_t* Bg = g_qw8 + (size_t)bn * KDIM;

    const int r0 = tid >> 2, c0 = tid & 3;
    const int r1 = r0 + 64;

    // PTX-verified lane mapping for m16n8k32.s8 via ldmatrix.x4.b16
    const int rowA_base = wm * 64 + (lane & 7) + ((lane >> 3) & 1) * 8;
    const int cA_off    = lane >> 4;
    const int rowB_base = wn * 32 + (lane & 7) + ((lane >> 4) << 3);
    const int cB_off    = (lane >> 3) & 1;

    int acc[4][4][4];
#pragma unroll
    for (int i = 0; i < 4; i++)
#pragma unroll
        for (int j = 0; j < 4; j++)
#pragma unroll
            for (int q = 0; q < 4; q++) acc[i][j][q] = 0;

    auto load_stage = [&](int st, int kt) {
        uint32_t sa = sAu + st * (BM * BK);
        uint32_t sb = sBu + st * (BN * BK);
        const int8_t* ab = Ag + kt * BK;
        const int8_t* bb = Bg + kt * BK;
        cp_async16(sa + swz(r0, c0), ab + (size_t)r0 * KDIM + c0 * 16);
        cp_async16(sa + swz(r1, c0), ab + (size_t)r1 * KDIM + c0 * 16);
        cp_async16(sb + swz(r0, c0), bb + (size_t)r0 * KDIM + c0 * 16);
        cp_async16(sb + swz(r1, c0), bb + (size_t)r1 * KDIM + c0 * 16);
    };

    auto compute_stage = [&](int st) {
        uint32_t sa = sAu + st * (BM * BK);
        uint32_t sb = sBu + st * (BN * BK);
#pragma unroll
        for (int kk = 0; kk < 2; ++kk) {
            uint32_t a[4][4];
#pragma unroll
            for (int mf = 0; mf < 4; ++mf) {
                int row = rowA_base + mf * 16;
                int c   = 2 * kk + cA_off;
                ldsm_x4(a[mf][0], a[mf][1], a[mf][2], a[mf][3], sa + swz(row, c));
            }
            uint32_t b[4][2];
#pragma unroll
            for (int nf2 = 0; nf2 < 2; ++nf2) {
                int row = rowB_base + nf2 * 16;
                int c   = 2 * kk + cB_off;
                uint32_t t0, t1, t2, t3;
                ldsm_x4(t0, t1, t2, t3, sb + swz(row, c));
                b[2 * nf2][0] = t0; b[2 * nf2][1] = t1;
                b[2 * nf2 + 1][0] = t2; b[2 * nf2 + 1][1] = t3;
            }
#pragma unroll
            for (int mf = 0; mf < 4; ++mf)
#pragma unroll
                for (int nf = 0; nf < 4; ++nf)
                    mma_s8(acc[mf][nf], a[mf], b[nf]);
        }
    };

    load_stage(0, 0); cp_commit();
    load_stage(1, 1); cp_commit();

    for (int kt = 0; kt < KT; ++kt) {
        cp_wait1();
        __syncthreads();
        if (kt + 2 < KT) load_stage((kt + 2) % STAGES, kt + 2);
        cp_commit();
        compute_stage(kt % STAGES);
    }

    // ---------------- epilogue (f32 output) ----------------
    const float v0 = *s0_p, v1 = *s1_p;
    const float ys    = fmaxf(v0, v1);      // y_scale ~ 4.7e-2
    const float alpha = fminf(v0, v1);      // alpha   ~ 6.0e-4
    const int grp = lane >> 2, qd = lane & 3;
#pragma unroll
    for (int mf = 0; mf < 4; ++mf) {
#pragma unroll
        for (int nf = 0; nf < 4; ++nf) {
            int row = bm + wm * 64 + mf * 16 + grp;
            int col = bn + wn * 32 + nf * 8 + 2 * qd;
            float b0f = (float)g_b8[col];
            float b1f = (float)g_b8[col + 1];
            float2 h0, h1;
            h0.x = requant(acc[mf][nf][0], b0f, alpha, ys);
            h0.y = requant(acc[mf][nf][1], b1f, alpha, ys);
            h1.x = requant(acc[mf][nf][2], b0f, alpha, ys);
            h1.y = requant(acc[mf][nf][3], b1f, alpha, ys);
            *reinterpret_cast<float2*>(out + (size_t)row * NOUT + col) = h0;
            *reinterpret_cast<float2*>(out + (size_t)(row + 8) * NOUT + col) = h1;
        }
    }
}

// ---------------- launch: bind inputs by SIZE (permutation-proof) ----------------
extern "C" void kernel_launch(void* const* d_in, const int* in_sizes, int n_in,
                              void* d_out, int out_size) {
    const void* x  = nullptr;   // float32 [8192,4096] (promoted fp16)
    const void* qw = nullptr;   // int32 [4096,4096] (promoted int8)
    const void* bi = nullptr;   // int32 [4096]
    const float* sc[2] = {nullptr, nullptr};
    int nsc = 0;
    for (int i = 0; i < n_in; ++i) {
        int sz = in_sizes[i];
        if      (sz == M_TOK * KDIM) x  = d_in[i];
        else if (sz == NOUT * KDIM)  qw = d_in[i];
        else if (sz == NOUT)         bi = d_in[i];
        else if (sz == 1 && nsc < 2) sc[nsc++] = (const float*)d_in[i];
    }
    float* out = (float*)d_out;

    const int n4 = (M_TOK * KDIM) / 4;   // float4 = 4 f32

    k_reset<<<1, 1>>>();
    k_detect<<<1, 256>>>(qw, bi);
    k_repack_qw<<<4096, 256>>>(qw);
    k_repack_b<<<1, 1024>>>(bi);
    k_absmax<<<1184, 256>>>((const uint4*)x, n4);
    k_quant<<<1184, 256>>>((const float4*)x, n4);

    dim3 grid(NOUT / BN, M_TOK / BM);    // (32, 64)
    k_gemm<<<grid, 256>>>(sc[0], sc[1], out);
}

// round 9
// speedup vs baseline: 4.7722x; 4.7722x over previous
#include <cuda_runtime.h>
#include <cuda_fp16.h>
#include <cuda_bf16.h>
#include <cstdint>

#define M_TOK 8192
#define KDIM  4096
#define NOUT  4096

// ---- arch-specific feature gate (tcgen05 only exists in sm_103a-specific pass) ----
#if (defined(__CUDA_ARCH_FEAT_SM103_ALL) || (defined(__CUDA_ARCH_SPECIFIC__) && (__CUDA_ARCH_SPECIFIC__ == 1030)))
#define HAS_TCGEN05 1
#else
#define HAS_TCGEN05 0
#endif

// ---- tcgen05 bf16 GEMM tiling ----
#define TBM 256
#define TBN 256
#define TKE 64                   // K elements per stage (= 128 bytes bf16 = SW128 row)
#define NKT (KDIM / TKE)         // 64 k-tiles
#define STG 3
#define STAGE_BYTES (512 * 128)  // (256 A + 256 B rows) x 128 B = 64 KB
#define SMEM_DYN (1024 + STG * STAGE_BYTES)

// ---- IMMA fallback tiling ----
#define IBM 128
#define IBN 128
#define IBK 64
#define IKT (KDIM / IBK)
#define ISTG 3

// ---------------- scratch (no allocs allowed) ----------------
__device__ __align__(16) int8_t  g_qx8[(size_t)M_TOK * KDIM];    // 32 MB (fallback)
__device__ __align__(16) int8_t  g_qw8[(size_t)NOUT * KDIM];     // 16 MB (fallback)
__device__ __align__(16) uint16_t g_qx16[(size_t)M_TOK * KDIM];  // 64 MB bf16 activations
__device__ __align__(16) uint16_t g_qw16[(size_t)NOUT * KDIM];   // 32 MB bf16 weights
__device__ __align__(16) int8_t  g_b8[NOUT];
__device__ unsigned g_absmax_bits;
__device__ unsigned g_qw_mode;   // 0=int8-native, 1=int32, 2=float32
__device__ unsigned g_b_mode;
__device__ unsigned g_use_tc;

// ---------------- generic helpers ----------------
__device__ __forceinline__ unsigned pack4(int a, int b, int c, int d) {
    return (unsigned)(a & 0xff) | ((unsigned)(b & 0xff) << 8) |
           ((unsigned)(c & 0xff) << 16) | ((unsigned)(d & 0xff) << 24);
}
__device__ __forceinline__ unsigned bf16pair(int a, int b) {
    __nv_bfloat162 p;
    p.x = __float2bfloat16_rn((float)a);   // exact: |a| <= 128
    p.y = __float2bfloat16_rn((float)b);
    return *reinterpret_cast<unsigned*>(&p);
}
__device__ __forceinline__ void cp_async16(uint32_t dst, const void* src) {
    asm volatile("cp.async.cg.shared.global [%0], [%1], 16;" :: "r"(dst), "l"(src));
}
__device__ __forceinline__ void cp_commit() { asm volatile("cp.async.commit_group;"); }
template <int N> __device__ __forceinline__ void cp_wait() {
    asm volatile("cp.async.wait_group %0;" :: "n"(N));
}
__device__ __forceinline__ uint32_t smem_u32(const void* p) {
    uint32_t a;
    asm("{ .reg .u64 t; cvta.to.shared.u64 t, %1; cvt.u32.u64 %0, t; }" : "=r"(a) : "l"(p));
    return a;
}
// Exact reference chain on an exact-integer f32 accumulator.
__device__ __forceinline__ float requantf(float af, float bf, float alpha, float ys) {
    float v = rintf(af * alpha) + bf;
    v = fminf(fmaxf(v, -128.0f), 127.0f) * ys;
    return __half2float(__float2half_rn(v));
}

// ---------------- kernel 0: reset + dtype detect + arch probe ----------------
__global__ void k_detect(const void* qw, const void* b) {
    int t = threadIdx.x;
    if (t == 0) {
        g_absmax_bits = 0u;
#if HAS_TCGEN05
        g_use_tc = 1u;
#else
        g_use_tc = 0u;
#endif
    }
    {
        int i32ok = 1, f32ok = 1;
#pragma unroll
        for (int s = 0; s < 4; ++s) {
            int idx = ((t * 4 + s) * 4099) & (4194304 - 1);
            unsigned w = ((const unsigned*)qw)[idx];
            i32ok &= ((int)w == (int)(signed char)(w & 0xffu)) ? 1 : 0;
            float f = __uint_as_float(w);
            f32ok &= (f == rintf(f) && fabsf(f) <= 256.0f) ? 1 : 0;
        }
        int ni = __syncthreads_count(i32ok);
        int nf = __syncthreads_count(f32ok);
        if (t == 0) g_qw_mode = (ni == 256) ? 1u : ((nf == 256) ? 2u : 0u);
    }
    {
        int i32ok = 1, f32ok = 1;
#pragma unroll
        for (int s = 0; s < 4; ++s) {
            int idx = t * 4 + s;
            unsigned w = ((const unsigned*)b)[idx];
            i32ok &= ((int)w == (int)(signed char)(w & 0xffu)) ? 1 : 0;
            float f = __uint_as_float(w);
            f32ok &= (f == rintf(f) && fabsf(f) <= 256.0f) ? 1 : 0;
        }
        int ni = __syncthreads_count(i32ok);
        int nf = __syncthreads_count(f32ok);
        if (t == 0) g_b_mode = (ni == 256) ? 1u : ((nf == 256) ? 2u : 0u);
    }
}

// ---------------- kernel 1: repack qw -> int8 + bf16 (+bias) ----------------
__global__ void k_repack(const void* qw, const void* b) {
    unsigned mode = g_qw_mode;
    unsigned* d8 = (unsigned*)g_qw8;
    uint2* d16 = (uint2*)g_qw16;
    int n4 = (NOUT * KDIM) / 4;
    int idx = blockIdx.x * blockDim.x + threadIdx.x;
    int stride = gridDim.x * blockDim.x;
    for (int i = idx; i < n4; i += stride) {
        int a, bq, c, d;
        if (mode == 1u) {
            int4 r = ((const int4*)qw)[i];
            a = r.x; bq = r.y; c = r.z; d = r.w;
        } else if (mode == 2u) {
            float4 r = ((const float4*)qw)[i];
            a = __float2int_rn(r.x); bq = __float2int_rn(r.y);
            c = __float2int_rn(r.z); d = __float2int_rn(r.w);
        } else {
            unsigned w = ((const unsigned*)qw)[i];
            a = (int)(signed char)(w); bq = (int)(signed char)(w >> 8);
            c = (int)(signed char)(w >> 16); d = (int)(signed char)(w >> 24);
        }
        d8[i] = pack4(a, bq, c, d);
        uint2 o16; o16.x = bf16pair(a, bq); o16.y = bf16pair(c, d);
        d16[i] = o16;
    }
    if (blockIdx.x == 0) {
        unsigned bm = g_b_mode;
        unsigned* bdst = (unsigned*)g_b8;
        for (int i = threadIdx.x; i < NOUT / 4; i += blockDim.x) {
            unsigned o;
            if (bm == 1u) {
                int4 r = ((const int4*)b)[i];
                o = pack4(r.x, r.y, r.z, r.w);
            } else if (bm == 2u) {
                float4 r = ((const float4*)b)[i];
                o = pack4(__float2int_rn(r.x), __float2int_rn(r.y),
                          __float2int_rn(r.z), __float2int_rn(r.w));
            } else {
                o = ((const unsigned*)b)[i];
            }
            bdst[i] = o;
        }
    }
}

// ---------------- kernel 2: absmax over f32 x ----------------
__global__ void k_absmax(const uint4* __restrict__ xv, int n4) {
    unsigned m = 0u;
    int idx = blockIdx.x * blockDim.x + threadIdx.x;
    int stride = gridDim.x * blockDim.x;
    for (int i = idx; i < n4; i += stride) {
        uint4 v = xv[i];
        m = max(m, v.x & 0x7fffffffu);
        m = max(m, v.y & 0x7fffffffu);
        m = max(m, v.z & 0x7fffffffu);
        m = max(m, v.w & 0x7fffffffu);
    }
#pragma unroll
    for (int o = 16; o; o >>= 1) m = max(m, __shfl_xor_sync(0xffffffffu, m, o));
    __shared__ unsigned sm[32];
    int lane = threadIdx.x & 31, wid = threadIdx.x >> 5;
    if (lane == 0) sm[wid] = m;
    __syncthreads();
    if (wid == 0) {
        unsigned v = (lane < (int)(blockDim.x >> 5)) ? sm[lane] : 0u;
#pragma unroll
        for (int o = 16; o; o >>= 1) v = max(v, __shfl_xor_sync(0xffffffffu, v, o));
        if (lane == 0) atomicMax(&g_absmax_bits, v);
    }
}

// ---------------- kernel 3: quantize f32 x -> int8 + bf16 ----------------
__device__ __forceinline__ int quant1(float f, float s, float r) {
    float q0 = f * r;
    float e  = fmaf(-s, q0, f);
    float q  = fmaf(r, e, q0);
    float qf = rintf(q);
    qf = fminf(fmaxf(qf, -128.0f), 127.0f);
    return (int)qf;
}

__global__ void k_quant(const float4* __restrict__ xv, int n4) {
    float amax = __uint_as_float(g_absmax_bits);
    float s = __fdiv_rn(amax, 127.0f);
    float r = __frcp_rn(s);
    int idx = blockIdx.x * blockDim.x + threadIdx.x;
    int stride = gridDim.x * blockDim.x;
    unsigned* q8 = reinterpret_cast<unsigned*>(g_qx8);
    uint2* q16 = reinterpret_cast<uint2*>(g_qx16);
    for (int i = idx; i < n4; i += stride) {
        float4 v = xv[i];
        int a = quant1(v.x, s, r), b = quant1(v.y, s, r);
        int c = quant1(v.z, s, r), d = quant1(v.w, s, r);
        q8[i] = pack4(a, b, c, d);
        uint2 o16; o16.x = bf16pair(a, b); o16.y = bf16pair(c, d);
        q16[i] = o16;
    }
}

// ================= kernel 4: IMMA fallback GEMM (skipped when tcgen05 live) =================
__device__ __forceinline__ int iswz(int row, int c) {
    return row * 64 + ((c ^ ((row >> 1) & 3)) << 4);
}
__device__ __forceinline__ void ldsm_x4(uint32_t& r0, uint32_t& r1, uint32_t& r2, uint32_t& r3, uint32_t addr) {
    asm volatile("ldmatrix.sync.aligned.m8n8.x4.shared.b16 {%0,%1,%2,%3}, [%4];"
                 : "=r"(r0), "=r"(r1), "=r"(r2), "=r"(r3) : "r"(addr));
}
__device__ __forceinline__ void mma_s8(int* c, const uint32_t* a, const uint32_t* b) {
    asm volatile(
        "mma.sync.aligned.m16n8k32.row.col.s32.s8.s8.s32 "
        "{%0,%1,%2,%3}, {%4,%5,%6,%7}, {%8,%9}, {%0,%1,%2,%3};"
        : "+r"(c[0]), "+r"(c[1]), "+r"(c[2]), "+r"(c[3])
        : "r"(a[0]), "r"(a[1]), "r"(a[2]), "r"(a[3]), "r"(b[0]), "r"(b[1]));
}
__device__ __forceinline__ float requant(int a, float bf, float alpha, float ys) {
    return requantf(__int2float_rn(a), bf, alpha, ys);
}

__global__ __launch_bounds__(256) void k_gemm_imma(
    const float* __restrict__ s0_p, const float* __restrict__ s1_p,
    float* __restrict__ out)
{
    if (g_use_tc) return;

    __shared__ __align__(16) int8_t sA[ISTG][IBM * IBK];
    __shared__ __align__(16) int8_t sB[ISTG][IBN * IBK];

    const int tid  = threadIdx.x;
    const int lane = tid & 31, warp = tid >> 5;
    const int wm = warp & 1;
    const int wn = warp >> 1;
    const int bm = blockIdx.y * IBM, bn = blockIdx.x * IBN;

    const uint32_t sAu = (uint32_t)__cvta_generic_to_shared(&sA[0][0]);
    const uint32_t sBu = (uint32_t)__cvta_generic_to_shared(&sB[0][0]);

    const int8_t* Ag = g_qx8 + (size_t)bm * KDIM;
    const int8_t* Bg = g_qw8 + (size_t)bn * KDIM;

    const int r0 = tid >> 2, c0 = tid & 3;
    const int r1 = r0 + 64;

    const int rowA_base = wm * 64 + (lane & 7) + ((lane >> 3) & 1) * 8;
    const int cA_off    = lane >> 4;
    const int rowB_base = wn * 32 + (lane & 7) + ((lane >> 4) << 3);
    const int cB_off    = (lane >> 3) & 1;

    int acc[4][4][4];
#pragma unroll
    for (int i = 0; i < 4; i++)
#pragma unroll
        for (int j = 0; j < 4; j++)
#pragma unroll
            for (int q = 0; q < 4; q++) acc[i][j][q] = 0;

    auto load_stage = [&](int st, int kt) {
        uint32_t sa = sAu + st * (IBM * IBK);
        uint32_t sb = sBu + st * (IBN * IBK);
        const int8_t* ab = Ag + kt * IBK;
        const int8_t* bb = Bg + kt * IBK;
        cp_async16(sa + iswz(r0, c0), ab + (size_t)r0 * KDIM + c0 * 16);
        cp_async16(sa + iswz(r1, c0), ab + (size_t)r1 * KDIM + c0 * 16);
        cp_async16(sb + iswz(r0, c0), bb + (size_t)r0 * KDIM + c0 * 16);
        cp_async16(sb + iswz(r1, c0), bb + (size_t)r1 * KDIM + c0 * 16);
    };

    auto compute_stage = [&](int st) {
        uint32_t sa = sAu + st * (IBM * IBK);
        uint32_t sb = sBu + st * (IBN * IBK);
#pragma unroll
        for (int kk = 0; kk < 2; ++kk) {
            uint32_t a[4][4];
#pragma unroll
            for (int mf = 0; mf < 4; ++mf) {
                int row = rowA_base + mf * 16;
                int c   = 2 * kk + cA_off;
                ldsm_x4(a[mf][0], a[mf][1], a[mf][2], a[mf][3], sa + iswz(row, c));
            }
            uint32_t b[4][2];
#pragma unroll
            for (int nf2 = 0; nf2 < 2; ++nf2) {
                int row = rowB_base + nf2 * 16;
                int c   = 2 * kk + cB_off;
                uint32_t t0, t1, t2, t3;
                ldsm_x4(t0, t1, t2, t3, sb + iswz(row, c));
                b[2 * nf2][0] = t0; b[2 * nf2][1] = t1;
                b[2 * nf2 + 1][0] = t2; b[2 * nf2 + 1][1] = t3;
            }
#pragma unroll
            for (int mf = 0; mf < 4; ++mf)
#pragma unroll
                for (int nf = 0; nf < 4; ++nf)
                    mma_s8(acc[mf][nf], a[mf], b[nf]);
        }
    };

    load_stage(0, 0); cp_commit();
    load_stage(1, 1); cp_commit();

    for (int kt = 0; kt < IKT; ++kt) {
        cp_wait<1>();
        __syncthreads();
        if (kt + 2 < IKT) load_stage((kt + 2) % ISTG, kt + 2);
        cp_commit();
        compute_stage(kt % ISTG);
    }

    const float v0 = *s0_p, v1 = *s1_p;
    const float ys    = fmaxf(v0, v1);
    const float alpha = fminf(v0, v1);
    const int grp = lane >> 2, qd = lane & 3;
#pragma unroll
    for (int mf = 0; mf < 4; ++mf) {
#pragma unroll
        for (int nf = 0; nf < 4; ++nf) {
            int row = bm + wm * 64 + mf * 16 + grp;
            int col = bn + wn * 32 + nf * 8 + 2 * qd;
            float b0f = (float)g_b8[col];
            float b1f = (float)g_b8[col + 1];
            float2 h0, h1;
            h0.x = requant(acc[mf][nf][0], b0f, alpha, ys);
            h0.y = requant(acc[mf][nf][1], b1f, alpha, ys);
            h1.x = requant(acc[mf][nf][2], b0f, alpha, ys);
            h1.y = requant(acc[mf][nf][3], b1f, alpha, ys);
            *reinterpret_cast<float2*>(out + (size_t)row * NOUT + col) = h0;
            *reinterpret_cast<float2*>(out + (size_t)(row + 8) * NOUT + col) = h1;
        }
    }
}

// ================= kernel 5: tcgen05 bf16 GEMM (exact integer math) =================
#if HAS_TCGEN05
__device__ __forceinline__ uint32_t elect_one() {
    uint32_t p;
    asm volatile("{\n\t.reg .pred q;\n\telect.sync _|q, 0xFFFFFFFF;\n\tselp.b32 %0, 1, 0, q;\n\t}" : "=r"(p));
    return p;
}
#define MBAR_INIT(a, c) asm volatile("mbarrier.init.shared.b64 [%0], %1;" :: "r"(a), "r"(c) : "memory")
#define MBAR_WAIT(a, ph) do { \
    uint32_t _m = (a), _p = (ph), _d; \
    asm volatile("{\n\t.reg .pred p;\n\tmbarrier.try_wait.parity.acquire.cta.shared::cta.b64 p, [%1], %2;\n\tselp.b32 %0, 1, 0, p;\n\t}" \
                 : "=r"(_d) : "r"(_m), "r"(_p) : "memory"); \
    if (!_d) { \
        asm volatile("{\n\t.reg .pred P;\n\tWL_%=:\n\tmbarrier.try_wait.parity.acquire.cta.shared::cta.b64 P, [%0], %1, 0x989680;\n\t@P bra.uni WD_%=;\n\tbra.uni WL_%=;\n\tWD_%=:\n\t}" \
                     :: "r"(_m), "r"(_p) : "memory"); \
    } } while (0)
#define TC_ALLOC(sm, n)  asm volatile("tcgen05.alloc.cta_group::1.sync.aligned.shared::cta.b32 [%0], %1;" :: "r"(sm), "r"(n) : "memory")
#define TC_DEALLOC(t, n) asm volatile("tcgen05.dealloc.cta_group::1.sync.aligned.b32 %0, %1;" :: "r"(t), "r"(n))
#define TC_COMMIT(mb)    asm volatile("tcgen05.commit.cta_group::1.mbarrier::arrive::one.shared::cluster.b64 [%0];" :: "r"(mb) : "memory")
#define TC_FENCE_AFTER() asm volatile("tcgen05.fence::after_thread_sync;" ::: "memory")
#define TC_WAIT_LD()     asm volatile("tcgen05.wait::ld.sync.aligned;" ::: "memory")
#define FENCE_ASYNC()    asm volatile("fence.proxy.async.shared::cta;" ::: "memory")
#define TC_LD_X32(r, a) \
    asm volatile("tcgen05.ld.sync.aligned.32x32b.x32.b32 " \
        "{%0,%1,%2,%3,%4,%5,%6,%7,%8,%9,%10,%11,%12,%13,%14,%15," \
        "%16,%17,%18,%19,%20,%21,%22,%23,%24,%25,%26,%27,%28,%29,%30,%31}, [%32];" \
        : "=r"((r)[0]),"=r"((r)[1]),"=r"((r)[2]),"=r"((r)[3]),"=r"((r)[4]),"=r"((r)[5]),"=r"((r)[6]),"=r"((r)[7]), \
          "=r"((r)[8]),"=r"((r)[9]),"=r"((r)[10]),"=r"((r)[11]),"=r"((r)[12]),"=r"((r)[13]),"=r"((r)[14]),"=r"((r)[15]), \
          "=r"((r)[16]),"=r"((r)[17]),"=r"((r)[18]),"=r"((r)[19]),"=r"((r)[20]),"=r"((r)[21]),"=r"((r)[22]),"=r"((r)[23]), \
          "=r"((r)[24]),"=r"((r)[25]),"=r"((r)[26]),"=r"((r)[27]),"=r"((r)[28]),"=r"((r)[29]),"=r"((r)[30]),"=r"((r)[31]) \
        : "r"(a))

// SW128 K-major smem descriptor: layout=2, version=1, SBO=64, LBO=1
static __device__ __forceinline__ uint64_t make_desc(uint32_t addr) {
    return ((uint64_t)2 << 61) | ((uint64_t)1 << 46) | ((uint64_t)64 << 32) |
           ((uint64_t)1 << 16) | ((uint64_t)(addr >> 4) & 0x3FFF);
}
// kind::f16, bf16 inputs, f32 accumulate (verified encoding from test_2cta_mma_bf16.cu)
__device__ __forceinline__ void tc_mma_bf16(uint32_t d, uint64_t a, uint64_t b, uint32_t idesc, uint32_t acc) {
    asm volatile(
        "{\n\t.reg .pred p;\n\tsetp.ne.u32 p, %5, 0;\n\t"
        "tcgen05.mma.cta_group::1.kind::f16 [%0], %1, %2, %3, {%4,%4,%4,%4}, p;\n\t}"
        :: "r"(d), "l"(a), "l"(b), "r"(idesc), "r"(0u), "r"(acc) : "memory");
}
// dtype=F32(1)<<4 | atype=BF16(1)<<7 | btype=BF16(1)<<10 | (N/8)<<17 | (M/16)<<24
#define IDESC_BF16 ((1u << 4) | (1u << 7) | (1u << 10) | ((TBN / 8) << 17) | ((128 / 16) << 24))
#endif  // HAS_TCGEN05

__global__ __launch_bounds__(256, 1) void k_gemm_tc(
    const float* __restrict__ s0_p, const float* __restrict__ s1_p,
    float* __restrict__ out)
{
#if HAS_TCGEN05
    extern __shared__ __align__(1024) uint8_t dsm[];
    const uint32_t sb = smem_u32(dsm);
    const int tid = threadIdx.x, wid = tid >> 5, lane = tid & 31;
    const int bm = blockIdx.y * TBM, bn = blockIdx.x * TBN;

    if (tid == 0) {
        MBAR_INIT(sb + 8, 1);
        MBAR_INIT(sb + 16, 1);
        MBAR_INIT(sb + 24, 1);
        MBAR_INIT(sb + 32, 1);
    }
    if (wid == 0) TC_ALLOC(sb, 512);
    __syncthreads();
    uint32_t tmem;
    asm volatile("ld.shared.b32 %0, [%1];" : "=r"(tmem) : "r"(sb));

    // bf16 rows: KDIM*2 bytes row stride; each k-tile advances 128 bytes (64 elems)
    const uint8_t* asrc0 = (const uint8_t*)g_qx16 + (size_t)bm * (KDIM * 2);
    const uint8_t* bsrc0 = (const uint8_t*)g_qw16 + (size_t)bn * (KDIM * 2);
    auto load_tile = [&](int s, int kt) {
        uint32_t stg = sb + 1024 + s * STAGE_BYTES;
        const uint8_t* aks = asrc0 + (size_t)kt * 128;
        const uint8_t* bks = bsrc0 + (size_t)kt * 128;
#pragma unroll
        for (int i = 0; i < 16; ++i) {
            int cid = tid + i * 256;
            int row = cid >> 3, c = cid & 7;
            const uint8_t* src = (row < 256) ? (aks + (size_t)row * (KDIM * 2) + c * 16)
                                             : (bks + (size_t)(row - 256) * (KDIM * 2) + c * 16);
            uint32_t dst = stg + row * 128 + ((c ^ (row & 7)) << 4);
            cp_async16(dst, src);
        }
        cp_commit();
    };

    int ph[STG] = {0, 0, 0};
    load_tile(0, 0); load_tile(1, 1); load_tile(2, 2);

    for (int kt = 0; kt < NKT; ++kt) {
        int s = kt % STG;
        if      (kt < NKT - 2) cp_wait<2>();
        else if (kt < NKT - 1) cp_wait<1>();
        else                   cp_wait<0>();
        __syncthreads();

        if (wid == 0) {
            FENCE_ASYNC();
            if (elect_one()) {
                uint32_t stg = sb + 1024 + s * STAGE_BYTES;
                uint64_t a0 = make_desc(stg);
                uint64_t a1 = make_desc(stg + 128 * 128);
                uint64_t bd = make_desc(stg + 256 * 128);
#pragma unroll
                for (int c = 0; c < 4; ++c) {     // 4 k-steps of K=16 bf16 (32 B = +2 units)
                    uint32_t acc = (kt > 0 || c > 0) ? 1u : 0u;
                    tc_mma_bf16(tmem,       a0 + c * 2, bd + c * 2, IDESC_BF16, acc);
                    tc_mma_bf16(tmem + 256, a1 + c * 2, bd + c * 2, IDESC_BF16, acc);
                }
                TC_COMMIT(sb + 8 + s * 8);
            }
        }
        int kt3 = kt + STG;
        if (kt3 < NKT) {
            MBAR_WAIT(sb + 8 + s * 8, ph[s]);   // stage reusable once its MMAs retired
            ph[s] ^= 1;
            load_tile(s, kt3);
        }
    }
    if (wid == 0 && elect_one()) TC_COMMIT(sb + 32);
    MBAR_WAIT(sb + 32, 0);
    TC_FENCE_AFTER();

    // epilogue: warps 0-3 -> tile rows 0-127 (tmem cols 0-255), warps 4-7 -> rows 128-255
    const float v0 = *s0_p, v1 = *s1_p;
    const float ys    = fmaxf(v0, v1);
    const float alpha = fminf(v0, v1);
    const int half = wid >> 2, wsub = wid & 3;
    const uint32_t tb = tmem + half * 256 + ((uint32_t)wsub << 21);
    const int mrow = bm + half * 128 + wsub * 32 + lane;
    float* orow = out + (size_t)mrow * NOUT + bn;

#pragma unroll
    for (int cc = 0; cc < 8; ++cc) {
        uint32_t r[32];
        TC_LD_X32(r, tb + cc * 32);
        TC_WAIT_LD();
        float4 o4;
#pragma unroll
        for (int j = 0; j < 32; j += 4) {
            int col = cc * 32 + j;
            o4.x = requantf(__uint_as_float(r[j]),     (float)g_b8[bn + col],     alpha, ys);
            o4.y = requantf(__uint_as_float(r[j + 1]), (float)g_b8[bn + col + 1], alpha, ys);
            o4.z = requantf(__uint_as_float(r[j + 2]), (float)g_b8[bn + col + 2], alpha, ys);
            o4.w = requantf(__uint_as_float(r[j + 3]), (float)g_b8[bn + col + 3], alpha, ys);
            *reinterpret_cast<float4*>(orow + col) = o4;
        }
    }

    __syncthreads();
    if (wid == 0) TC_DEALLOC(tmem, 512);
#endif  // HAS_TCGEN05
}

// ---------------- launch: bind inputs by SIZE (permutation-proof) ----------------
extern "C" void kernel_launch(void* const* d_in, const int* in_sizes, int n_in,
                              void* d_out, int out_size) {
    const void* x  = nullptr;
    const void* qw = nullptr;
    const void* bi = nullptr;
    const float* sc[2] = {nullptr, nullptr};
    int nsc = 0;
    for (int i = 0; i < n_in; ++i) {
        int sz = in_sizes[i];
        if      (sz == M_TOK * KDIM) x  = d_in[i];
        else if (sz == NOUT * KDIM)  qw = d_in[i];
        else if (sz == NOUT)         bi = d_in[i];
        else if (sz == 1 && nsc < 2) sc[nsc++] = (const float*)d_in[i];
    }
    float* out = (float*)d_out;

    static int attr_done = 0;
    if (!attr_done) {
        cudaFuncSetAttribute(k_gemm_tc, cudaFuncAttributeMaxDynamicSharedMemorySize, SMEM_DYN);
        attr_done = 1;
    }

    const int n4 = (M_TOK * KDIM) / 4;

    k_detect<<<1, 256>>>(qw, bi);                         // launch 0
    k_repack<<<4096, 256>>>(qw, bi);                      // launch 1
    k_absmax<<<1184, 256>>>((const uint4*)x, n4);         // launch 2
    k_quant<<<1184, 256>>>((const float4*)x, n4);         // launch 3

    dim3 gi(NOUT / IBN, M_TOK / IBM);                     // (32, 64)
    k_gemm_imma<<<gi, 256>>>(sc[0], sc[1], out);          // launch 4 (early-exit if tc)

    dim3 gt(NOUT / TBN, M_TOK / TBM);                     // (16, 32)
    k_gemm_tc<<<gt, 256, SMEM_DYN>>>(sc[0], sc[1], out);  // launch 5 (ncu -s 5 hits this)
}

// round 10
// speedup vs baseline: 4.9094x; 1.0288x over previous
#include <cuda_runtime.h>
#include <cuda_fp16.h>
#include <cuda_bf16.h>
#include <cstdint>

#define M_TOK 8192
#define KDIM  4096
#define NOUT  4096

// ---- arch-specific feature gate ----
#if (defined(__CUDA_ARCH_FEAT_SM103_ALL) || (defined(__CUDA_ARCH_SPECIFIC__) && (__CUDA_ARCH_SPECIFIC__ == 1030)))
#define HAS_TCGEN05 1
#else
#define HAS_TCGEN05 0
#endif

// ---- tcgen05 cg2 bf16 GEMM tiling ----
#define CTBM 256                 // cluster tile M (128 per CTA)
#define CTBN 512                 // cluster tile N (2 dispatches of 256)
#define NKT  64                  // k-tiles of 64 bf16 (=128 B rows)
#define STG  4
#define A_ROWS 128
#define B_ROWS 256
#define STAGE_BYTES ((A_ROWS + B_ROWS) * 128)   // 48 KB
#define SMEM_DYN (1024 + STG * STAGE_BYTES)     // 193 KB

// ---- IMMA fallback tiling ----
#define IBM 128
#define IBN 128
#define IBK 64
#define IKT (KDIM / IBK)
#define ISTG 3

// ---------------- scratch ----------------
__device__ __align__(16) int8_t  g_qx8[(size_t)M_TOK * KDIM];
__device__ __align__(16) int8_t  g_qw8[(size_t)NOUT * KDIM];
__device__ __align__(16) uint16_t g_qx16[(size_t)M_TOK * KDIM];
__device__ __align__(16) uint16_t g_qw16[(size_t)NOUT * KDIM];
__device__ __align__(16) int8_t  g_b8[NOUT];
__device__ unsigned g_absmax_bits;
__device__ unsigned g_qw_mode;
__device__ unsigned g_b_mode;
__device__ unsigned g_use_tc;

// ---------------- generic helpers ----------------
__device__ __forceinline__ unsigned pack4(int a, int b, int c, int d) {
    return (unsigned)(a & 0xff) | ((unsigned)(b & 0xff) << 8) |
           ((unsigned)(c & 0xff) << 16) | ((unsigned)(d & 0xff) << 24);
}
__device__ __forceinline__ unsigned bf16pair(int a, int b) {
    __nv_bfloat162 p;
    p.x = __float2bfloat16_rn((float)a);
    p.y = __float2bfloat16_rn((float)b);
    return *reinterpret_cast<unsigned*>(&p);
}
__device__ __forceinline__ void cp_async16(uint32_t dst, const void* src) {
    asm volatile("cp.async.cg.shared.global [%0], [%1], 16;" :: "r"(dst), "l"(src));
}
__device__ __forceinline__ void cp_commit() { asm volatile("cp.async.commit_group;"); }
template <int N> __device__ __forceinline__ void cp_wait() {
    asm volatile("cp.async.wait_group %0;" :: "n"(N));
}
__device__ __forceinline__ uint32_t smem_u32(const void* p) {
    uint32_t a;
    asm("{ .reg .u64 t; cvta.to.shared.u64 t, %1; cvt.u32.u64 %0, t; }" : "=r"(a) : "l"(p));
    return a;
}
__device__ __forceinline__ float requantf(float af, float bf, float alpha, float ys) {
    float v = rintf(af * alpha) + bf;
    v = fminf(fmaxf(v, -128.0f), 127.0f) * ys;
    return __half2float(__float2half_rn(v));
}

// ---------------- kernel 0: reset + dtype detect + arch probe ----------------
__global__ void k_detect(const void* qw, const void* b) {
    int t = threadIdx.x;
    if (t == 0) {
        g_absmax_bits = 0u;
#if HAS_TCGEN05
        g_use_tc = 1u;
#else
        g_use_tc = 0u;
#endif
    }
    {
        int i32ok = 1, f32ok = 1;
#pragma unroll
        for (int s = 0; s < 4; ++s) {
            int idx = ((t * 4 + s) * 4099) & (4194304 - 1);
            unsigned w = ((const unsigned*)qw)[idx];
            i32ok &= ((int)w == (int)(signed char)(w & 0xffu)) ? 1 : 0;
            float f = __uint_as_float(w);
            f32ok &= (f == rintf(f) && fabsf(f) <= 256.0f) ? 1 : 0;
        }
        int ni = __syncthreads_count(i32ok);
        int nf = __syncthreads_count(f32ok);
        if (t == 0) g_qw_mode = (ni == 256) ? 1u : ((nf == 256) ? 2u : 0u);
    }
    {
        int i32ok = 1, f32ok = 1;
#pragma unroll
        for (int s = 0; s < 4; ++s) {
            int idx = t * 4 + s;
            unsigned w = ((const unsigned*)b)[idx];
            i32ok &= ((int)w == (int)(signed char)(w & 0xffu)) ? 1 : 0;
            float f = __uint_as_float(w);
            f32ok &= (f == rintf(f) && fabsf(f) <= 256.0f) ? 1 : 0;
        }
        int ni = __syncthreads_count(i32ok);
        int nf = __syncthreads_count(f32ok);
        if (t == 0) g_b_mode = (ni == 256) ? 1u : ((nf == 256) ? 2u : 0u);
    }
}

// ---------------- kernel 1: repack qw -> bf16 (+int8 only for fallback) ----------------
__global__ void k_repack(const void* qw, const void* b) {
    unsigned mode = g_qw_mode;
    unsigned tc = g_use_tc;
    unsigned* d8 = (unsigned*)g_qw8;
    uint2* d16 = (uint2*)g_qw16;
    int n4 = (NOUT * KDIM) / 4;
    int idx = blockIdx.x * blockDim.x + threadIdx.x;
    int stride = gridDim.x * blockDim.x;
    for (int i = idx; i < n4; i += stride) {
        int a, bq, c, d;
        if (mode == 1u) {
            int4 r = ((const int4*)qw)[i];
            a = r.x; bq = r.y; c = r.z; d = r.w;
        } else if (mode == 2u) {
            float4 r = ((const float4*)qw)[i];
            a = __float2int_rn(r.x); bq = __float2int_rn(r.y);
            c = __float2int_rn(r.z); d = __float2int_rn(r.w);
        } else {
            unsigned w = ((const unsigned*)qw)[i];
            a = (int)(signed char)(w); bq = (int)(signed char)(w >> 8);
            c = (int)(signed char)(w >> 16); d = (int)(signed char)(w >> 24);
        }
        if (!tc) d8[i] = pack4(a, bq, c, d);
        uint2 o16; o16.x = bf16pair(a, bq); o16.y = bf16pair(c, d);
        d16[i] = o16;
    }
    if (blockIdx.x == 0) {
        unsigned bm = g_b_mode;
        unsigned* bdst = (unsigned*)g_b8;
        for (int i = threadIdx.x; i < NOUT / 4; i += blockDim.x) {
            unsigned o;
            if (bm == 1u) {
                int4 r = ((const int4*)b)[i];
                o = pack4(r.x, r.y, r.z, r.w);
            } else if (bm == 2u) {
                float4 r = ((const float4*)b)[i];
                o = pack4(__float2int_rn(r.x), __float2int_rn(r.y),
                          __float2int_rn(r.z), __float2int_rn(r.w));
            } else {
                o = ((const unsigned*)b)[i];
            }
            bdst[i] = o;
        }
    }
}

// ---------------- kernel 2: absmax over f32 x ----------------
__global__ void k_absmax(const uint4* __restrict__ xv, int n4) {
    unsigned m = 0u;
    int idx = blockIdx.x * blockDim.x + threadIdx.x;
    int stride = gridDim.x * blockDim.x;
    for (int i = idx; i < n4; i += stride) {
        uint4 v = xv[i];
        m = max(m, v.x & 0x7fffffffu);
        m = max(m, v.y & 0x7fffffffu);
        m = max(m, v.z & 0x7fffffffu);
        m = max(m, v.w & 0x7fffffffu);
    }
#pragma unroll
    for (int o = 16; o; o >>= 1) m = max(m, __shfl_xor_sync(0xffffffffu, m, o));
    __shared__ unsigned sm[32];
    int lane = threadIdx.x & 31, wid = threadIdx.x >> 5;
    if (lane == 0) sm[wid] = m;
    __syncthreads();
    if (wid == 0) {
        unsigned v = (lane < (int)(blockDim.x >> 5)) ? sm[lane] : 0u;
#pragma unroll
        for (int o = 16; o; o >>= 1) v = max(v, __shfl_xor_sync(0xffffffffu, v, o));
        if (lane == 0) atomicMax(&g_absmax_bits, v);
    }
}

// ---------------- kernel 3: quantize f32 x -> bf16 (+int8 only for fallback) ----------------
__device__ __forceinline__ int quant1(float f, float s, float r) {
    float q0 = f * r;
    float e  = fmaf(-s, q0, f);
    float q  = fmaf(r, e, q0);
    float qf = rintf(q);
    qf = fminf(fmaxf(qf, -128.0f), 127.0f);
    return (int)qf;
}

__global__ void k_quant(const float4* __restrict__ xv, int n4) {
    float amax = __uint_as_float(g_absmax_bits);
    float s = __fdiv_rn(amax, 127.0f);
    float r = __frcp_rn(s);
    unsigned tc = g_use_tc;
    int idx = blockIdx.x * blockDim.x + threadIdx.x;
    int stride = gridDim.x * blockDim.x;
    unsigned* q8 = reinterpret_cast<unsigned*>(g_qx8);
    uint2* q16 = reinterpret_cast<uint2*>(g_qx16);
    for (int i = idx; i < n4; i += stride) {
        float4 v = xv[i];
        int a = quant1(v.x, s, r), b = quant1(v.y, s, r);
        int c = quant1(v.z, s, r), d = quant1(v.w, s, r);
        if (!tc) q8[i] = pack4(a, b, c, d);
        uint2 o16; o16.x = bf16pair(a, b); o16.y = bf16pair(c, d);
        q16[i] = o16;
    }
}

// ================= kernel 4: IMMA fallback GEMM (skipped when tcgen05 live) =================
__device__ __forceinline__ int iswz(int row, int c) {
    return row * 64 + ((c ^ ((row >> 1) & 3)) << 4);
}
__device__ __forceinline__ void ldsm_x4(uint32_t& r0, uint32_t& r1, uint32_t& r2, uint32_t& r3, uint32_t addr) {
    asm volatile("ldmatrix.sync.aligned.m8n8.x4.shared.b16 {%0,%1,%2,%3}, [%4];"
                 : "=r"(r0), "=r"(r1), "=r"(r2), "=r"(r3) : "r"(addr));
}
__device__ __forceinline__ void mma_s8(int* c, const uint32_t* a, const uint32_t* b) {
    asm volatile(
        "mma.sync.aligned.m16n8k32.row.col.s32.s8.s8.s32 "
        "{%0,%1,%2,%3}, {%4,%5,%6,%7}, {%8,%9}, {%0,%1,%2,%3};"
        : "+r"(c[0]), "+r"(c[1]), "+r"(c[2]), "+r"(c[3])
        : "r"(a[0]), "r"(a[1]), "r"(a[2]), "r"(a[3]), "r"(b[0]), "r"(b[1]));
}
__device__ __forceinline__ float requant(int a, float bf, float alpha, float ys) {
    return requantf(__int2float_rn(a), bf, alpha, ys);
}

__global__ __launch_bounds__(256) void k_gemm_imma(
    const float* __restrict__ s0_p, const float* __restrict__ s1_p,
    float* __restrict__ out)
{
    if (g_use_tc) return;

    __shared__ __align__(16) int8_t sA[ISTG][IBM * IBK];
    __shared__ __align__(16) int8_t sB[ISTG][IBN * IBK];

    const int tid  = threadIdx.x;
    const int lane = tid & 31, warp = tid >> 5;
    const int wm = warp & 1;
    const int wn = warp >> 1;
    const int bm = blockIdx.y * IBM, bn = blockIdx.x * IBN;

    const uint32_t sAu = (uint32_t)__cvta_generic_to_shared(&sA[0][0]);
    const uint32_t sBu = (uint32_t)__cvta_generic_to_shared(&sB[0][0]);

    const int8_t* Ag = g_qx8 + (size_t)bm * KDIM;
    const int8_t* Bg = g_qw8 + (size_t)bn * KDIM;

    const int r0 = tid >> 2, c0 = tid & 3;
    const int r1 = r0 + 64;

    const int rowA_base = wm * 64 + (lane & 7) + ((lane >> 3) & 1) * 8;
    const int cA_off    = lane >> 4;
    const int rowB_base = wn * 32 + (lane & 7) + ((lane >> 4) << 3);
    const int cB_off    = (lane >> 3) & 1;

    int acc[4][4][4];
#pragma unroll
    for (int i = 0; i < 4; i++)
#pragma unroll
        for (int j = 0; j < 4; j++)
#pragma unroll
            for (int q = 0; q < 4; q++) acc[i][j][q] = 0;

    auto load_stage = [&](int st, int kt) {
        uint32_t sa = sAu + st * (IBM * IBK);
        uint32_t sb = sBu + st * (IBN * IBK);
        const int8_t* ab = Ag + kt * IBK;
        const int8_t* bb = Bg + kt * IBK;
        cp_async16(sa + iswz(r0, c0), ab + (size_t)r0 * KDIM + c0 * 16);
        cp_async16(sa + iswz(r1, c0), ab + (size_t)r1 * KDIM + c0 * 16);
        cp_async16(sb + iswz(r0, c0), bb + (size_t)r0 * KDIM + c0 * 16);
        cp_async16(sb + iswz(r1, c0), bb + (size_t)r1 * KDIM + c0 * 16);
    };

    auto compute_stage = [&](int st) {
        uint32_t sa = sAu + st * (IBM * IBK);
        uint32_t sb = sBu + st * (IBN * IBK);
#pragma unroll
        for (int kk = 0; kk < 2; ++kk) {
            uint32_t a[4][4];
#pragma unroll
            for (int mf = 0; mf < 4; ++mf) {
                int row = rowA_base + mf * 16;
                int c   = 2 * kk + cA_off;
                ldsm_x4(a[mf][0], a[mf][1], a[mf][2], a[mf][3], sa + iswz(row, c));
            }
            uint32_t b[4][2];
#pragma unroll
            for (int nf2 = 0; nf2 < 2; ++nf2) {
                int row = rowB_base + nf2 * 16;
                int c   = 2 * kk + cB_off;
                uint32_t t0, t1, t2, t3;
                ldsm_x4(t0, t1, t2, t3, sb + iswz(row, c));
                b[2 * nf2][0] = t0; b[2 * nf2][1] = t1;
                b[2 * nf2 + 1][0] = t2; b[2 * nf2 + 1][1] = t3;
            }
#pragma unroll
            for (int mf = 0; mf < 4; ++mf)
#pragma unroll
                for (int nf = 0; nf < 4; ++nf)
                    mma_s8(acc[mf][nf], a[mf], b[nf]);
        }
    };

    load_stage(0, 0); cp_commit();
    load_stage(1, 1); cp_commit();

    for (int kt = 0; kt < IKT; ++kt) {
        cp_wait<1>();
        __syncthreads();
        if (kt + 2 < IKT) load_stage((kt + 2) % ISTG, kt + 2);
        cp_commit();
        compute_stage(kt % ISTG);
    }

    const float v0 = *s0_p, v1 = *s1_p;
    const float ys    = fmaxf(v0, v1);
    const float alpha = fminf(v0, v1);
    const int grp = lane >> 2, qd = lane & 3;
#pragma unroll
    for (int mf = 0; mf < 4; ++mf) {
#pragma unroll
        for (int nf = 0; nf < 4; ++nf) {
            int row = bm + wm * 64 + mf * 16 + grp;
            int col = bn + wn * 32 + nf * 8 + 2 * qd;
            float b0f = (float)g_b8[col];
            float b1f = (float)g_b8[col + 1];
            float2 h0, h1;
            h0.x = requant(acc[mf][nf][0], b0f, alpha, ys);
            h0.y = requant(acc[mf][nf][1], b1f, alpha, ys);
            h1.x = requant(acc[mf][nf][2], b0f, alpha, ys);
            h1.y = requant(acc[mf][nf][3], b1f, alpha, ys);
            *reinterpret_cast<float2*>(out + (size_t)row * NOUT + col) = h0;
            *reinterpret_cast<float2*>(out + (size_t)(row + 8) * NOUT + col) = h1;
        }
    }
}

// ================= kernel 5: tcgen05 cg2 bf16 GEMM (exact integer math) =================
#if HAS_TCGEN05
__device__ __forceinline__ uint32_t elect_one() {
    uint32_t p;
    asm volatile("{\n\t.reg .pred q;\n\telect.sync _|q, 0xFFFFFFFF;\n\tselp.b32 %0, 1, 0, q;\n\t}" : "=r"(p));
    return p;
}
#define MBAR_INIT(a, c) asm volatile("mbarrier.init.shared.b64 [%0], %1;" :: "r"(a), "r"(c) : "memory")
#define MBAR_WAIT(a, ph) do { \
    uint32_t _m = (a), _p = (ph), _d; \
    asm volatile("{\n\t.reg .pred p;\n\tmbarrier.try_wait.parity.acquire.cta.shared::cta.b64 p, [%1], %2;\n\tselp.b32 %0, 1, 0, p;\n\t}" \
                 : "=r"(_d) : "r"(_m), "r"(_p) : "memory"); \
    if (!_d) { \
        asm volatile("{\n\t.reg .pred P;\n\tWL_%=:\n\tmbarrier.try_wait.parity.acquire.cta.shared::cta.b64 P, [%0], %1, 0x989680;\n\t@P bra.uni WD_%=;\n\tbra.uni WL_%=;\n\tWD_%=:\n\t}" \
                     :: "r"(_m), "r"(_p) : "memory"); \
    } } while (0)
#define MBAR_ARRIVE_RANK0(addr) \
    asm volatile("{\n\t.reg .b32 ra;\n\tmapa.shared::cluster.u32 ra, %0, %1;\n\t" \
                 "mbarrier.arrive.shared::cluster.b64 _, [ra];\n\t}" \
                 :: "r"(addr), "r"(0) : "memory")
#define TC_ALLOC_CG2(sm, n)  asm volatile("tcgen05.alloc.cta_group::2.sync.aligned.shared::cta.b32 [%0], %1;" :: "r"(sm), "r"(n) : "memory")
#define TC_RELINQ_CG2()      asm volatile("tcgen05.relinquish_alloc_permit.cta_group::2.sync.aligned;")
#define TC_DEALLOC_CG2(t, n) asm volatile("tcgen05.dealloc.cta_group::2.sync.aligned.b32 %0, %1;" :: "r"(t), "r"(n))
#define TC_COMMIT_MC2(mb)    asm volatile("tcgen05.commit.cta_group::2.mbarrier::arrive::one.shared::cluster.multicast::cluster.b64 [%0], %1;" :: "r"(mb), "h"((uint16_t)3) : "memory")
#define TC_FENCE_AFTER()     asm volatile("tcgen05.fence::after_thread_sync;" ::: "memory")
#define TC_WAIT_LD()         asm volatile("tcgen05.wait::ld.sync.aligned;" ::: "memory")
#define FENCE_ASYNC()        asm volatile("fence.proxy.async.shared::cta;" ::: "memory")
#define CLUSTER_SYNC() do { \
    asm volatile("barrier.cluster.arrive.aligned;" ::: "memory"); \
    asm volatile("barrier.cluster.wait.aligned;" ::: "memory"); } while (0)
#define TC_LD_X32(r, a) \
    asm volatile("tcgen05.ld.sync.aligned.32x32b.x32.b32 " \
        "{%0,%1,%2,%3,%4,%5,%6,%7,%8,%9,%10,%11,%12,%13,%14,%15," \
        "%16,%17,%18,%19,%20,%21,%22,%23,%24,%25,%26,%27,%28,%29,%30,%31}, [%32];" \
        : "=r"((r)[0]),"=r"((r)[1]),"=r"((r)[2]),"=r"((r)[3]),"=r"((r)[4]),"=r"((r)[5]),"=r"((r)[6]),"=r"((r)[7]), \
          "=r"((r)[8]),"=r"((r)[9]),"=r"((r)[10]),"=r"((r)[11]),"=r"((r)[12]),"=r"((r)[13]),"=r"((r)[14]),"=r"((r)[15]), \
          "=r"((r)[16]),"=r"((r)[17]),"=r"((r)[18]),"=r"((r)[19]),"=r"((r)[20]),"=r"((r)[21]),"=r"((r)[22]),"=r"((r)[23]), \
          "=r"((r)[24]),"=r"((r)[25]),"=r"((r)[26]),"=r"((r)[27]),"=r"((r)[28]),"=r"((r)[29]),"=r"((r)[30]),"=r"((r)[31]) \
        : "r"(a))

// SW128 K-major smem descriptor: layout=2, version=1, SBO=64, LBO=1
static __device__ __forceinline__ uint64_t make_desc(uint32_t addr) {
    return ((uint64_t)2 << 61) | ((uint64_t)1 << 46) | ((uint64_t)64 << 32) |
           ((uint64_t)1 << 16) | ((uint64_t)(addr >> 4) & 0x3FFF);
}
// cg2 kind::f16 bf16 MMA (encoding from test_2cta_mma_bf16.cu)
__device__ __forceinline__ void tc_mma_bf16_cg2(uint32_t d, uint64_t a, uint64_t b, uint32_t idesc, uint32_t acc) {
    asm volatile(
        "{\n\t.reg .pred p;\n\tsetp.ne.u32 p, %5, 0;\n\t"
        "tcgen05.mma.cta_group::2.kind::f16 [%0], %1, %2, %3, {%4,%4,%4,%4,%4,%4,%4,%4}, p;\n\t}"
        :: "r"(d), "l"(a), "l"(b), "r"(idesc), "r"(0u), "r"(acc) : "memory");
}
// dtype=F32(1)<<4 | atype=BF16(1)<<7 | btype=BF16(1)<<10 | (N/8)<<17 | (M_TOTAL/16)<<24
#define IDESC_CG2 ((1u << 4) | (1u << 7) | (1u << 10) | ((256u / 8) << 17) | ((256u / 16) << 24))
#endif  // HAS_TCGEN05

__global__ __launch_bounds__(256, 1) __cluster_dims__(2, 1, 1)
void k_gemm_tc(const float* __restrict__ s0_p, const float* __restrict__ s1_p,
               float* __restrict__ out)
{
#if HAS_TCGEN05
    extern __shared__ __align__(1024) uint8_t dsm[];
    const uint32_t sb = smem_u32(dsm);
    const int tid = threadIdx.x, wid = tid >> 5, lane = tid & 31;
    uint32_t rank;
    asm("mov.u32 %0, %%cluster_ctarank;" : "=r"(rank));
    const int tile_n = blockIdx.x >> 1, tile_m = blockIdx.y;

    // header: tmem ptr @0; full[s] @8+8s (count 2); empty[s] @40+8s (count 1); final @72
    if (tid == 0) {
#pragma unroll
        for (int s = 0; s < STG; ++s) {
            MBAR_INIT(sb + 8 + s * 8, 2);
            MBAR_INIT(sb + 40 + s * 8, 1);
        }
        MBAR_INIT(sb + 72, 1);
    }
    if (wid == 0) TC_ALLOC_CG2(sb, 512);
    __syncthreads();
    uint32_t tmem;
    asm volatile("ld.shared.b32 %0, [%1];" : "=r"(tmem) : "r"(sb));
    CLUSTER_SYNC();   // peer mbarriers live before any cluster arrive / peer SMEM read

    // A: this CTA's 128 M-rows. B: cg2 N-split — for N-dispatch d, CTA rank r
    // supplies global N-rows tile_n*512 + d*256 + r*128 + [0,128).
    const uint8_t* abase = (const uint8_t*)g_qx16 +
        ((size_t)tile_m * CTBM + rank * A_ROWS) * (size_t)(KDIM * 2);
    const uint8_t* bbase = (const uint8_t*)g_qw16 +
        ((size_t)tile_n * CTBN + rank * 128) * (size_t)(KDIM * 2);

    auto load_tile = [&](int s, int kt) {
        uint32_t stg = sb + 1024 + s * STAGE_BYTES;
        const uint8_t* ak = abase + (size_t)kt * 128;
        const uint8_t* bk = bbase + (size_t)kt * 128;
#pragma unroll
        for (int i = 0; i < 12; ++i) {             // 384 rows x 8 chunks / 256 thr
            int cid = tid + i * 256;
            int row = cid >> 3, c = cid & 7;
            const uint8_t* src;
            if (row < A_ROWS) {
                src = ak + (size_t)row * (KDIM * 2) + c * 16;
            } else {
                int j = row - A_ROWS;              // local B slot 0..255
                int d = j >> 7, subr = j & 127;
                src = bk + (size_t)(d * 256 + subr) * (KDIM * 2) + c * 16;
            }
            cp_async16(stg + row * 128 + ((c ^ (row & 7)) << 4), src);
        }
        cp_commit();
    };

    load_tile(0, 0); load_tile(1, 1); load_tile(2, 2); load_tile(3, 3);

    int phf[STG] = {0, 0, 0, 0};
    int phe[STG] = {0, 0, 0, 0};

    for (int kt = 0; kt < NKT; ++kt) {
        int s = kt & (STG - 1);
        int rem = NKT - 1 - kt;
        if      (rem >= 3) cp_wait<3>();
        else if (rem == 2) cp_wait<2>();
        else if (rem == 1) cp_wait<1>();
        else               cp_wait<0>();
        __syncthreads();
        if (tid == 0) {
            FENCE_ASYNC();
            MBAR_ARRIVE_RANK0(sb + 8 + s * 8);     // both CTAs arrive on leader full[s]
        }
        if (rank == 0 && wid == 0) {
            if (elect_one()) {
                MBAR_WAIT(sb + 8 + s * 8, phf[s]); // both CTAs' stage s resident
                phf[s] ^= 1;
                uint32_t stg = sb + 1024 + s * STAGE_BYTES;
                uint64_t ad = make_desc(stg);
                uint64_t b0 = make_desc(stg + A_ROWS * 128);
                uint64_t b1 = make_desc(stg + A_ROWS * 128 + 128 * 128);
#pragma unroll
                for (int c = 0; c < 4; ++c) {      // 4 k-steps of K=16 (32 B = +2 units)
                    uint32_t acc = (kt > 0 || c > 0) ? 1u : 0u;
                    tc_mma_bf16_cg2(tmem,       ad + c * 2, b0 + c * 2, IDESC_CG2, acc);
                    tc_mma_bf16_cg2(tmem + 256, ad + c * 2, b1 + c * 2, IDESC_CG2, acc);
                }
                if (kt + STG < NKT) TC_COMMIT_MC2(sb + 40 + s * 8);
            }
        }
        int kt3 = kt + STG;
        if (kt3 < NKT) {
            MBAR_WAIT(sb + 40 + s * 8, phe[s]);    // stage reusable once kt's MMAs retired
            phe[s] ^= 1;
            load_tile(s, kt3);
        }
    }
    if (rank == 0 && wid == 0 && elect_one()) TC_COMMIT_MC2(sb + 72);
    MBAR_WAIT(sb + 72, 0);
    TC_FENCE_AFTER();

    // epilogue: warps 0-3 -> D cols 0-255, warps 4-7 -> cols 256-511; lanes = M rows
    const float v0 = *s0_p, v1 = *s1_p;
    const float ys    = fmaxf(v0, v1);
    const float alpha = fminf(v0, v1);
    const int chalf = wid >> 2, wsub = wid & 3;
    const uint32_t tb = tmem + chalf * 256 + ((uint32_t)wsub << 21);
    const int mrow = tile_m * CTBM + (int)rank * A_ROWS + wsub * 32 + lane;
    const int cbase = tile_n * CTBN + chalf * 256;
    float* orow = out + (size_t)mrow * NOUT + cbase;

#pragma unroll
    for (int cc = 0; cc < 8; ++cc) {
        uint32_t r[32];
        TC_LD_X32(r, tb + cc * 32);
        TC_WAIT_LD();
        float4 o4;
#pragma unroll
        for (int j = 0; j < 32; j += 4) {
            int col = cc * 32 + j;
            o4.x = requantf(__uint_as_float(r[j]),     (float)g_b8[cbase + col],     alpha, ys);
            o4.y = requantf(__uint_as_float(r[j + 1]), (float)g_b8[cbase + col + 1], alpha, ys);
            o4.z = requantf(__uint_as_float(r[j + 2]), (float)g_b8[cbase + col + 2], alpha, ys);
            o4.w = requantf(__uint_as_float(r[j + 3]), (float)g_b8[cbase + col + 3], alpha, ys);
            *reinterpret_cast<float4*>(orow + col) = o4;
        }
    }

    __syncthreads();
    if (wid == 0) {
        TC_RELINQ_CG2();
        TC_DEALLOC_CG2(tmem, 512);
    }
    CLUSTER_SYNC();   // no CTA exits while peer MMAs/commits could touch its SMEM
#endif  // HAS_TCGEN05
}

// ---------------- launch: bind inputs by SIZE (permutation-proof) ----------------
extern "C" void kernel_launch(void* const* d_in, const int* in_sizes, int n_in,
                              void* d_out, int out_size) {
    const void* x  = nullptr;
    const void* qw = nullptr;
    const void* bi = nullptr;
    const float* sc[2] = {nullptr, nullptr};
    int nsc = 0;
    for (int i = 0; i < n_in; ++i) {
        int sz = in_sizes[i];
        if      (sz == M_TOK * KDIM) x  = d_in[i];
        else if (sz == NOUT * KDIM)  qw = d_in[i];
        else if (sz == NOUT)         bi = d_in[i];
        else if (sz == 1 && nsc < 2) sc[nsc++] = (const float*)d_in[i];
    }
    float* out = (float*)d_out;

    static int attr_done = 0;
    if (!attr_done) {
        cudaFuncSetAttribute(k_gemm_tc, cudaFuncAttributeMaxDynamicSharedMemorySize, SMEM_DYN);
        attr_done = 1;
    }

    const int n4 = (M_TOK * KDIM) / 4;

    k_detect<<<1, 256>>>(qw, bi);                         // launch 0
    k_repack<<<4096, 256>>>(qw, bi);                      // launch 1
    k_absmax<<<1184, 256>>>((const uint4*)x, n4);         // launch 2
    k_quant<<<1184, 256>>>((const float4*)x, n4);         // launch 3

    dim3 gi(NOUT / IBN, M_TOK / IBM);                     // (32, 64)
    k_gemm_imma<<<gi, 256>>>(sc[0], sc[1], out);          // launch 4 (early-exit if tc)

    dim3 gt((NOUT / CTBN) * 2, M_TOK / CTBM);             // (16, 32), clusters of 2 on x
    k_gemm_tc<<<gt, 256, SMEM_DYN>>>(sc[0], sc[1], out);  // launch 5
}

// round 11
// speedup vs baseline: 5.3772x; 1.0953x over previous
#include <cuda_runtime.h>
#include <cuda_fp16.h>
#include <cuda_bf16.h>
#include <cstdint>

#define M_TOK 8192
#define KDIM  4096
#define NOUT  4096

// ---- arch-specific feature gate ----
#if (defined(__CUDA_ARCH_FEAT_SM103_ALL) || (defined(__CUDA_ARCH_SPECIFIC__) && (__CUDA_ARCH_SPECIFIC__ == 1030)))
#define HAS_TCGEN05 1
#else
#define HAS_TCGEN05 0
#endif

// ---- tcgen05 cg2 bf16 GEMM tiling ----
#define CTBM 256                 // cluster tile M (128 per CTA)
#define CTBN 512                 // cluster tile N (2 dispatches of 256)
#define NKT  32                  // k-tiles of 128 bf16 (256 B per row, 2 SW128 atom-cols)
#define STG  2
#define A_ROWS 128
#define B_ROWS 256
#define STAGE_BYTES ((A_ROWS + B_ROWS) * 256)   // 96 KB
#define SMEM_DYN (1024 + STG * STAGE_BYTES)     // 193 KB
#define KB2 (KDIM * 2)           // bf16 row stride in bytes

// ---- IMMA fallback tiling ----
#define IBM 128
#define IBN 128
#define IBK 64
#define IKT (KDIM / IBK)
#define ISTG 3

// ---------------- scratch ----------------
__device__ __align__(16) int8_t  g_qx8[(size_t)M_TOK * KDIM];
__device__ __align__(16) int8_t  g_qw8[(size_t)NOUT * KDIM];
__device__ __align__(16) uint16_t g_qx16[(size_t)M_TOK * KDIM];
__device__ __align__(16) uint16_t g_qw16[(size_t)NOUT * KDIM];
__device__ __align__(16) int8_t  g_b8[NOUT];
__device__ unsigned g_absmax_bits;

// ---------------- generic helpers ----------------
__device__ __forceinline__ unsigned pack4(int a, int b, int c, int d) {
    return (unsigned)(a & 0xff) | ((unsigned)(b & 0xff) << 8) |
           ((unsigned)(c & 0xff) << 16) | ((unsigned)(d & 0xff) << 24);
}
__device__ __forceinline__ unsigned bf16pair(int a, int b) {
    __nv_bfloat162 p;
    p.x = __float2bfloat16_rn((float)a);
    p.y = __float2bfloat16_rn((float)b);
    return *reinterpret_cast<unsigned*>(&p);
}
__device__ __forceinline__ void cp_async16(uint32_t dst, const void* src) {
    asm volatile("cp.async.cg.shared.global [%0], [%1], 16;" :: "r"(dst), "l"(src));
}
__device__ __forceinline__ void cp_commit() { asm volatile("cp.async.commit_group;"); }
template <int N> __device__ __forceinline__ void cp_wait() {
    asm volatile("cp.async.wait_group %0;" :: "n"(N));
}
__device__ __forceinline__ uint32_t smem_u32(const void* p) {
    uint32_t a;
    asm("{ .reg .u64 t; cvta.to.shared.u64 t, %1; cvt.u32.u64 %0, t; }" : "=r"(a) : "l"(p));
    return a;
}
__device__ __forceinline__ float requantf(float af, float bf, float alpha, float ys) {
    float v = rintf(af * alpha) + bf;
    v = fminf(fmaxf(v, -128.0f), 127.0f) * ys;
    return __half2float(__float2half_rn(v));
}

// deterministic per-block dtype consensus (same samples in every block)
// returns 1=int32, 2=float32, 0=int8-native
__device__ __forceinline__ unsigned detect_mode(const unsigned* p, int mask, int mult) {
    int t = threadIdx.x;
    int i32ok = 1, f32ok = 1;
#pragma unroll
    for (int s = 0; s < 4; ++s) {
        int idx = ((t * 4 + s) * mult) & mask;
        unsigned w = p[idx];
        i32ok &= ((int)w == (int)(signed char)(w & 0xffu)) ? 1 : 0;
        float f = __uint_as_float(w);
        f32ok &= (f == rintf(f) && fabsf(f) <= 256.0f) ? 1 : 0;
    }
    int ni = __syncthreads_count(i32ok);
    int nf = __syncthreads_count(f32ok);
    return (ni == 256) ? 1u : ((nf == 256) ? 2u : 0u);
}

// ---------------- launch 0: repack (detect inline) + bias + absmax reset ----------------
__global__ void k_repack(const void* qw, const void* b) {
    unsigned mode = detect_mode((const unsigned*)qw, 4194304 - 1, 4099);
    if (blockIdx.x == 0 && threadIdx.x == 0) g_absmax_bits = 0u;
    unsigned* d8 = (unsigned*)g_qw8;
    uint2* d16 = (uint2*)g_qw16;
    int n4 = (NOUT * KDIM) / 4;
    int idx = blockIdx.x * blockDim.x + threadIdx.x;
    int stride = gridDim.x * blockDim.x;
    for (int i = idx; i < n4; i += stride) {
        int a, bq, c, d;
        if (mode == 1u) {
            int4 r = ((const int4*)qw)[i];
            a = r.x; bq = r.y; c = r.z; d = r.w;
        } else if (mode == 2u) {
            float4 r = ((const float4*)qw)[i];
            a = __float2int_rn(r.x); bq = __float2int_rn(r.y);
            c = __float2int_rn(r.z); d = __float2int_rn(r.w);
        } else {
            unsigned w = ((const unsigned*)qw)[i];
            a = (int)(signed char)(w); bq = (int)(signed char)(w >> 8);
            c = (int)(signed char)(w >> 16); d = (int)(signed char)(w >> 24);
        }
#if !HAS_TCGEN05
        d8[i] = pack4(a, bq, c, d);
#else
        (void)d8;
#endif
        uint2 o16; o16.x = bf16pair(a, bq); o16.y = bf16pair(c, d);
        d16[i] = o16;
    }
    if (blockIdx.x == 0) {
        unsigned bm = detect_mode((const unsigned*)b, 1024 - 1, 4);
        unsigned* bdst = (unsigned*)g_b8;
        for (int i = threadIdx.x; i < NOUT / 4; i += blockDim.x) {
            unsigned o;
            if (bm == 1u) {
                int4 r = ((const int4*)b)[i];
                o = pack4(r.x, r.y, r.z, r.w);
            } else if (bm == 2u) {
                float4 r = ((const float4*)b)[i];
                o = pack4(__float2int_rn(r.x), __float2int_rn(r.y),
                          __float2int_rn(r.z), __float2int_rn(r.w));
            } else {
                o = ((const unsigned*)b)[i];
            }
            bdst[i] = o;
        }
    }
}

// ---------------- launch 1: absmax over f32 x ----------------
__global__ void k_absmax(const uint4* __restrict__ xv, int n4) {
    unsigned m = 0u;
    int idx = blockIdx.x * blockDim.x + threadIdx.x;
    int stride = gridDim.x * blockDim.x;
    for (int i = idx; i < n4; i += stride) {
        uint4 v = xv[i];
        m = max(m, v.x & 0x7fffffffu);
        m = max(m, v.y & 0x7fffffffu);
        m = max(m, v.z & 0x7fffffffu);
        m = max(m, v.w & 0x7fffffffu);
    }
#pragma unroll
    for (int o = 16; o; o >>= 1) m = max(m, __shfl_xor_sync(0xffffffffu, m, o));
    __shared__ unsigned sm[32];
    int lane = threadIdx.x & 31, wid = threadIdx.x >> 5;
    if (lane == 0) sm[wid] = m;
    __syncthreads();
    if (wid == 0) {
        unsigned v = (lane < (int)(blockDim.x >> 5)) ? sm[lane] : 0u;
#pragma unroll
        for (int o = 16; o; o >>= 1) v = max(v, __shfl_xor_sync(0xffffffffu, v, o));
        if (lane == 0) atomicMax(&g_absmax_bits, v);
    }
}

// ---------------- launch 2: quantize f32 x -> bf16 (+int8 only on fallback) ----------------
__device__ __forceinline__ int quant1(float f, float s, float r) {
    float q0 = f * r;
    float e  = fmaf(-s, q0, f);
    float q  = fmaf(r, e, q0);
    float qf = rintf(q);
    qf = fminf(fmaxf(qf, -128.0f), 127.0f);
    return (int)qf;
}

__global__ void k_quant(const float4* __restrict__ xv, int n4) {
    float amax = __uint_as_float(g_absmax_bits);
    float s = __fdiv_rn(amax, 127.0f);
    float r = __frcp_rn(s);
    int idx = blockIdx.x * blockDim.x + threadIdx.x;
    int stride = gridDim.x * blockDim.x;
    unsigned* q8 = reinterpret_cast<unsigned*>(g_qx8);
    uint2* q16 = reinterpret_cast<uint2*>(g_qx16);
    for (int i = idx; i < n4; i += stride) {
        float4 v = xv[i];
        int a = quant1(v.x, s, r), b = quant1(v.y, s, r);
        int c = quant1(v.z, s, r), d = quant1(v.w, s, r);
#if !HAS_TCGEN05
        q8[i] = pack4(a, b, c, d);
#else
        (void)q8;
#endif
        uint2 o16; o16.x = bf16pair(a, b); o16.y = bf16pair(c, d);
        q16[i] = o16;
    }
}

// ================= tcgen05 cg2 bf16 GEMM (launch 3) =================
#if HAS_TCGEN05
__device__ __forceinline__ uint32_t elect_one() {
    uint32_t p;
    asm volatile("{\n\t.reg .pred q;\n\telect.sync _|q, 0xFFFFFFFF;\n\tselp.b32 %0, 1, 0, q;\n\t}" : "=r"(p));
    return p;
}
#define MBAR_INIT(a, c) asm volatile("mbarrier.init.shared.b64 [%0], %1;" :: "r"(a), "r"(c) : "memory")
#define MBAR_WAIT(a, ph) do { \
    uint32_t _m = (a), _p = (ph), _d; \
    asm volatile("{\n\t.reg .pred p;\n\tmbarrier.try_wait.parity.acquire.cta.shared::cta.b64 p, [%1], %2;\n\tselp.b32 %0, 1, 0, p;\n\t}" \
                 : "=r"(_d) : "r"(_m), "r"(_p) : "memory"); \
    if (!_d) { \
        asm volatile("{\n\t.reg .pred P;\n\tWL_%=:\n\tmbarrier.try_wait.parity.acquire.cta.shared::cta.b64 P, [%0], %1, 0x989680;\n\t@P bra.uni WD_%=;\n\tbra.uni WL_%=;\n\tWD_%=:\n\t}" \
                     :: "r"(_m), "r"(_p) : "memory"); \
    } } while (0)
#define MBAR_ARRIVE_RANK0(addr) \
    asm volatile("{\n\t.reg .b32 ra;\n\tmapa.shared::cluster.u32 ra, %0, %1;\n\t" \
                 "mbarrier.arrive.shared::cluster.b64 _, [ra];\n\t}" \
                 :: "r"(addr), "r"(0) : "memory")
#define TC_ALLOC_CG2(sm, n)  asm volatile("tcgen05.alloc.cta_group::2.sync.aligned.shared::cta.b32 [%0], %1;" :: "r"(sm), "r"(n) : "memory")
#define TC_RELINQ_CG2()      asm volatile("tcgen05.relinquish_alloc_permit.cta_group::2.sync.aligned;")
#define TC_DEALLOC_CG2(t, n) asm volatile("tcgen05.dealloc.cta_group::2.sync.aligned.b32 %0, %1;" :: "r"(t), "r"(n))
#define TC_COMMIT_MC2(mb)    asm volatile("tcgen05.commit.cta_group::2.mbarrier::arrive::one.shared::cluster.multicast::cluster.b64 [%0], %1;" :: "r"(mb), "h"((uint16_t)3) : "memory")
#define TC_FENCE_AFTER()     asm volatile("tcgen05.fence::after_thread_sync;" ::: "memory")
#define TC_WAIT_LD()         asm volatile("tcgen05.wait::ld.sync.aligned;" ::: "memory")
#define FENCE_ASYNC()        asm volatile("fence.proxy.async.shared::cta;" ::: "memory")
#define CLUSTER_SYNC() do { \
    asm volatile("barrier.cluster.arrive.aligned;" ::: "memory"); \
    asm volatile("barrier.cluster.wait.aligned;" ::: "memory"); } while (0)
#define TC_LD_X32(r, a) \
    asm volatile("tcgen05.ld.sync.aligned.32x32b.x32.b32 " \
        "{%0,%1,%2,%3,%4,%5,%6,%7,%8,%9,%10,%11,%12,%13,%14,%15," \
        "%16,%17,%18,%19,%20,%21,%22,%23,%24,%25,%26,%27,%28,%29,%30,%31}, [%32];" \
        : "=r"((r)[0]),"=r"((r)[1]),"=r"((r)[2]),"=r"((r)[3]),"=r"((r)[4]),"=r"((r)[5]),"=r"((r)[6]),"=r"((r)[7]), \
          "=r"((r)[8]),"=r"((r)[9]),"=r"((r)[10]),"=r"((r)[11]),"=r"((r)[12]),"=r"((r)[13]),"=r"((r)[14]),"=r"((r)[15]), \
          "=r"((r)[16]),"=r"((r)[17]),"=r"((r)[18]),"=r"((r)[19]),"=r"((r)[20]),"=r"((r)[21]),"=r"((r)[22]),"=r"((r)[23]), \
          "=r"((r)[24]),"=r"((r)[25]),"=r"((r)[26]),"=r"((r)[27]),"=r"((r)[28]),"=r"((r)[29]),"=r"((r)[30]),"=r"((r)[31]) \
        : "r"(a))

// SW128 K-major smem descriptor: layout=2, version=1, SBO=64, LBO=1
static __device__ __forceinline__ uint64_t make_desc(uint32_t addr) {
    return ((uint64_t)2 << 61) | ((uint64_t)1 << 46) | ((uint64_t)64 << 32) |
           ((uint64_t)1 << 16) | ((uint64_t)(addr >> 4) & 0x3FFF);
}
__device__ __forceinline__ void tc_mma_bf16_cg2(uint32_t d, uint64_t a, uint64_t b, uint32_t idesc, uint32_t acc) {
    asm volatile(
        "{\n\t.reg .pred p;\n\tsetp.ne.u32 p, %5, 0;\n\t"
        "tcgen05.mma.cta_group::2.kind::f16 [%0], %1, %2, %3, {%4,%4,%4,%4,%4,%4,%4,%4}, p;\n\t}"
        :: "r"(d), "l"(a), "l"(b), "r"(idesc), "r"(0u), "r"(acc) : "memory");
}
// dtype=F32(1)<<4 | atype=BF16(1)<<7 | btype=BF16(1)<<10 | (N/8)<<17 | (M_TOTAL/16)<<24
#define IDESC_CG2 ((1u << 4) | (1u << 7) | (1u << 10) | ((256u / 8) << 17) | ((256u / 16) << 24))
#endif  // HAS_TCGEN05

__global__ __launch_bounds__(256, 1) __cluster_dims__(2, 1, 1)
void k_gemm_tc(const float* __restrict__ s0_p, const float* __restrict__ s1_p,
               float* __restrict__ out)
{
#if HAS_TCGEN05
    extern __shared__ __align__(1024) uint8_t dsm[];
    const uint32_t sb = smem_u32(dsm);
    const int tid = threadIdx.x, wid = tid >> 5, lane = tid & 31;
    uint32_t rank;
    asm("mov.u32 %0, %%cluster_ctarank;" : "=r"(rank));
    const int tile_n = blockIdx.x >> 1, tile_m = blockIdx.y;

    // header: tmem ptr @0; full[s] @8+8s (count 2); empty[s] @24+8s (count 1); final @40
    if (tid == 0) {
#pragma unroll
        for (int s = 0; s < STG; ++s) {
            MBAR_INIT(sb + 8 + s * 8, 2);
            MBAR_INIT(sb + 24 + s * 8, 1);
        }
        MBAR_INIT(sb + 40, 1);
    }
    if (wid == 0) TC_ALLOC_CG2(sb, 512);
    __syncthreads();
    uint32_t tmem;
    asm volatile("ld.shared.b32 %0, [%1];" : "=r"(tmem) : "r"(sb));
    CLUSTER_SYNC();

    // A: this CTA's 128 M-rows. B (cg2 N-split): for N-dispatch d, CTA rank r supplies
    // global N-rows tile_n*512 + d*256 + r*128 + [0,128).
    const uint8_t* abase = (const uint8_t*)g_qx16 +
        ((size_t)tile_m * CTBM + rank * A_ROWS) * (size_t)KB2;
    const uint8_t* bbase = (const uint8_t*)g_qw16 +
        ((size_t)tile_n * CTBN + rank * 128) * (size_t)KB2;

    // Stage layout (96 KB): A @0: 2 atom-cols x (128 rows x 128 B) = 32 KB (acol stride 16384)
    //                       B @32768: 2 atom-cols x (256 rows x 128 B) = 64 KB (acol stride 32768)
    auto load_tile = [&](int s, int kt) {
        uint32_t stg = sb + 1024 + s * STAGE_BYTES;
        const uint8_t* ak = abase + (size_t)kt * 256;
        const uint8_t* bk = bbase + (size_t)kt * 256;
#pragma unroll
        for (int i = 0; i < 24; ++i) {             // 384 rows x 16 chunks / 256 thr
            int cid = tid + i * 256;
            int row = cid >> 4, c16 = cid & 15;
            int acol = c16 >> 3, cc = c16 & 7;
            const uint8_t* src;
            uint32_t dst;
            if (row < A_ROWS) {
                src = ak + (size_t)row * KB2 + c16 * 16;
                dst = stg + acol * 16384 + row * 128 + ((cc ^ (row & 7)) << 4);
            } else {
                int j = row - A_ROWS;              // local B slot 0..255
                int d = j >> 7, subr = j & 127;
                src = bk + (size_t)(d * 256 + subr) * KB2 + c16 * 16;
                dst = stg + 32768 + acol * 32768 + j * 128 + ((cc ^ (j & 7)) << 4);
            }
            cp_async16(dst, src);
        }
        cp_commit();
    };

    load_tile(0, 0); load_tile(1, 1);

    int phf[STG] = {0, 0};
    int phe[STG] = {0, 0};

    for (int kt = 0; kt < NKT; ++kt) {
        int s = kt & 1;
        if (kt < NKT - 1) cp_wait<1>(); else cp_wait<0>();
        __syncthreads();
        if (tid == 0) {
            FENCE_ASYNC();
            MBAR_ARRIVE_RANK0(sb + 8 + s * 8);     // both CTAs arrive on leader full[s]
        }
        if (rank == 0 && wid == 0) {
            if (elect_one()) {
                MBAR_WAIT(sb + 8 + s * 8, phf[s]);
                phf[s] ^= 1;
                uint32_t stg = sb + 1024 + s * STAGE_BYTES;
                uint64_t ad = make_desc(stg);
                uint64_t bd = make_desc(stg + 32768);
#pragma unroll
                for (int c = 0; c < 8; ++c) {      // 8 k-steps of K=16 (acol = c>>2)
                    uint32_t acc = (kt > 0 || c > 0) ? 1u : 0u;
                    uint64_t ao = ad + (uint64_t)((c >> 2) * 1024 + (c & 3) * 2);
                    uint64_t bo = bd + (uint64_t)((c >> 2) * 2048 + (c & 3) * 2);
                    tc_mma_bf16_cg2(tmem,       ao, bo,        IDESC_CG2, acc);
                    tc_mma_bf16_cg2(tmem + 256, ao, bo + 1024, IDESC_CG2, acc);
                }
                if (kt + STG < NKT) TC_COMMIT_MC2(sb + 24 + s * 8);
            }
        }
        int kt2 = kt + STG;
        if (kt2 < NKT) {
            MBAR_WAIT(sb + 24 + s * 8, phe[s]);    // stage reusable once kt's MMAs retired
            phe[s] ^= 1;
            load_tile(s, kt2);
        }
    }
    if (rank == 0 && wid == 0 && elect_one()) TC_COMMIT_MC2(sb + 40);
    MBAR_WAIT(sb + 40, 0);
    TC_FENCE_AFTER();

    // epilogue: warps 0-3 -> D cols 0-255, warps 4-7 -> cols 256-511; lanes = M rows
    const float v0 = *s0_p, v1 = *s1_p;
    const float ys    = fmaxf(v0, v1);
    const float alpha = fminf(v0, v1);
    const int chalf = wid >> 2, wsub = wid & 3;
    const uint32_t tb = tmem + chalf * 256 + ((uint32_t)wsub << 21);
    const int mrow = tile_m * CTBM + (int)rank * A_ROWS + wsub * 32 + lane;
    const int cbase = tile_n * CTBN + chalf * 256;
    float* orow = out + (size_t)mrow * NOUT + cbase;

#pragma unroll
    for (int cc = 0; cc < 8; ++cc) {
        uint32_t r[32];
        TC_LD_X32(r, tb + cc * 32);
        TC_WAIT_LD();
        float4 o4;
#pragma unroll
        for (int j = 0; j < 32; j += 4) {
            int col = cc * 32 + j;
            o4.x = requantf(__uint_as_float(r[j]),     (float)g_b8[cbase + col],     alpha, ys);
            o4.y = requantf(__uint_as_float(r[j + 1]), (float)g_b8[cbase + col + 1], alpha, ys);
            o4.z = requantf(__uint_as_float(r[j + 2]), (float)g_b8[cbase + col + 2], alpha, ys);
            o4.w = requantf(__uint_as_float(r[j + 3]), (float)g_b8[cbase + col + 3], alpha, ys);
            *reinterpret_cast<float4*>(orow + col) = o4;
        }
    }

    __syncthreads();
    if (wid == 0) {
        TC_RELINQ_CG2();
        TC_DEALLOC_CG2(tmem, 512);
    }
    CLUSTER_SYNC();
#endif  // HAS_TCGEN05
}

// ================= IMMA fallback GEMM (launch 4; compile-time no-op when tc) =================
__device__ __forceinline__ int iswz(int row, int c) {
    return row * 64 + ((c ^ ((row >> 1) & 3)) << 4);
}
__device__ __forceinline__ void ldsm_x4(uint32_t& r0, uint32_t& r1, uint32_t& r2, uint32_t& r3, uint32_t addr) {
    asm volatile("ldmatrix.sync.aligned.m8n8.x4.shared.b16 {%0,%1,%2,%3}, [%4];"
                 : "=r"(r0), "=r"(r1), "=r"(r2), "=r"(r3) : "r"(addr));
}
__device__ __forceinline__ void mma_s8(int* c, const uint32_t* a, const uint32_t* b) {
    asm volatile(
        "mma.sync.aligned.m16n8k32.row.col.s32.s8.s8.s32 "
        "{%0,%1,%2,%3}, {%4,%5,%6,%7}, {%8,%9}, {%0,%1,%2,%3};"
        : "+r"(c[0]), "+r"(c[1]), "+r"(c[2]), "+r"(c[3])
        : "r"(a[0]), "r"(a[1]), "r"(a[2]), "r"(a[3]), "r"(b[0]), "r"(b[1]));
}

__global__ __launch_bounds__(256) void k_gemm_imma(
    const float* __restrict__ s0_p, const float* __restrict__ s1_p,
    float* __restrict__ out)
{
#if !HAS_TCGEN05
    __shared__ __align__(16) int8_t sA[ISTG][IBM * IBK];
    __shared__ __align__(16) int8_t sB[ISTG][IBN * IBK];

    const int tid  = threadIdx.x;
    const int lane = tid & 31, warp = tid >> 5;
    const int wm = warp & 1;
    const int wn = warp >> 1;
    const int bm = blockIdx.y * IBM, bn = blockIdx.x * IBN;

    const uint32_t sAu = (uint32_t)__cvta_generic_to_shared(&sA[0][0]);
    const uint32_t sBu = (uint32_t)__cvta_generic_to_shared(&sB[0][0]);

    const int8_t* Ag = g_qx8 + (size_t)bm * KDIM;
    const int8_t* Bg = g_qw8 + (size_t)bn * KDIM;

    const int r0 = tid >> 2, c0 = tid & 3;
    const int r1 = r0 + 64;

    const int rowA_base = wm * 64 + (lane & 7) + ((lane >> 3) & 1) * 8;
    const int cA_off    = lane >> 4;
    const int rowB_base = wn * 32 + (lane & 7) + ((lane >> 4) << 3);
    const int cB_off    = (lane >> 3) & 1;

    int acc[4][4][4];
#pragma unroll
    for (int i = 0; i < 4; i++)
#pragma unroll
        for (int j = 0; j < 4; j++)
#pragma unroll
            for (int q = 0; q < 4; q++) acc[i][j][q] = 0;

    auto load_stage = [&](int st, int kt) {
        uint32_t sa = sAu + st * (IBM * IBK);
        uint32_t sb = sBu + st * (IBN * IBK);
        const int8_t* ab = Ag + kt * IBK;
        const int8_t* bb = Bg + kt * IBK;
        cp_async16(sa + iswz(r0, c0), ab + (size_t)r0 * KDIM + c0 * 16);
        cp_async16(sa + iswz(r1, c0), ab + (size_t)r1 * KDIM + c0 * 16);
        cp_async16(sb + iswz(r0, c0), bb + (size_t)r0 * KDIM + c0 * 16);
        cp_async16(sb + iswz(r1, c0), bb + (size_t)r1 * KDIM + c0 * 16);
    };

    auto compute_stage = [&](int st) {
        uint32_t sa = sAu + st * (IBM * IBK);
        uint32_t sb = sBu + st * (IBN * IBK);
#pragma unroll
        for (int kk = 0; kk < 2; ++kk) {
            uint32_t a[4][4];
#pragma unroll
            for (int mf = 0; mf < 4; ++mf) {
                int row = rowA_base + mf * 16;
                int c   = 2 * kk + cA_off;
                ldsm_x4(a[mf][0], a[mf][1], a[mf][2], a[mf][3], sa + iswz(row, c));
            }
            uint32_t b[4][2];
#pragma unroll
            for (int nf2 = 0; nf2 < 2; ++nf2) {
                int row = rowB_base + nf2 * 16;
                int c   = 2 * kk + cB_off;
                uint32_t t0, t1, t2, t3;
                ldsm_x4(t0, t1, t2, t3, sb + iswz(row, c));
                b[2 * nf2][0] = t0; b[2 * nf2][1] = t1;
                b[2 * nf2 + 1][0] = t2; b[2 * nf2 + 1][1] = t3;
            }
#pragma unroll
            for (int mf = 0; mf < 4; ++mf)
#pragma unroll
                for (int nf = 0; nf < 4; ++nf)
                    mma_s8(acc[mf][nf], a[mf], b[nf]);
        }
    };

    load_stage(0, 0); cp_commit();
    load_stage(1, 1); cp_commit();

    for (int kt = 0; kt < IKT; ++kt) {
        cp_wait<1>();
        __syncthreads();
        if (kt + 2 < IKT) load_stage((kt + 2) % ISTG, kt + 2);
        cp_commit();
        compute_stage(kt % ISTG);
    }

    const float v0 = *s0_p, v1 = *s1_p;
    const float ys    = fmaxf(v0, v1);
    const float alpha = fminf(v0, v1);
    const int grp = lane >> 2, qd = lane & 3;
#pragma unroll
    for (int mf = 0; mf < 4; ++mf) {
#pragma unroll
        for (int nf = 0; nf < 4; ++nf) {
            int row = bm + wm * 64 + mf * 16 + grp;
            int col = bn + wn * 32 + nf * 8 + 2 * qd;
            float b0f = (float)g_b8[col];
            float b1f = (float)g_b8[col + 1];
            float2 h0, h1;
            h0.x = requantf(__int2float_rn(acc[mf][nf][0]), b0f, alpha, ys);
            h0.y = requantf(__int2float_rn(acc[mf][nf][1]), b1f, alpha, ys);
            h1.x = requantf(__int2float_rn(acc[mf][nf][2]), b0f, alpha, ys);
            h1.y = requantf(__int2float_rn(acc[mf][nf][3]), b1f, alpha, ys);
            *reinterpret_cast<float2*>(out + (size_t)row * NOUT + col) = h0;
            *reinterpret_cast<float2*>(out + (size_t)(row + 8) * NOUT + col) = h1;
        }
    }
#endif  // !HAS_TCGEN05
}

// ---------------- launch: bind inputs by SIZE (permutation-proof) ----------------
extern "C" void kernel_launch(void* const* d_in, const int* in_sizes, int n_in,
                              void* d_out, int out_size) {
    const void* x  = nullptr;
    const void* qw = nullptr;
    const void* bi = nullptr;
    const float* sc[2] = {nullptr, nullptr};
    int nsc = 0;
    for (int i = 0; i < n_in; ++i) {
        int sz = in_sizes[i];
        if      (sz == M_TOK * KDIM) x  = d_in[i];
        else if (sz == NOUT * KDIM)  qw = d_in[i];
        else if (sz == NOUT)         bi = d_in[i];
        else if (sz == 1 && nsc < 2) sc[nsc++] = (const float*)d_in[i];
    }
    float* out = (float*)d_out;

    static int attr_done = 0;
    if (!attr_done) {
        cudaFuncSetAttribute(k_gemm_tc, cudaFuncAttributeMaxDynamicSharedMemorySize, SMEM_DYN);
        attr_done = 1;
    }

    const int n4 = (M_TOK * KDIM) / 4;

    k_repack<<<4096, 256>>>(qw, bi);                      // launch 0 (detect inline)
    k_absmax<<<1184, 256>>>((const uint4*)x, n4);         // launch 1
    k_quant<<<1184, 256>>>((const float4*)x, n4);         // launch 2

    dim3 gt((NOUT / CTBN) * 2, M_TOK / CTBM);             // (16, 32), clusters of 2 on x
    k_gemm_tc<<<gt, 256, SMEM_DYN>>>(sc[0], sc[1], out);  // launch 3  <- ncu capture slot

    dim3 gi(NOUT / IBN, M_TOK / IBM);                     // (32, 64)
    k_gemm_imma<<<gi, 256>>>(sc[0], sc[1], out);          // launch 4 (no-op when tc)
}

// round 12
// speedup vs baseline: 6.8556x; 1.2749x over previous
#include <cuda_runtime.h>
#include <cuda.h>
#include <cuda_fp16.h>
#include <cuda_bf16.h>
#include <cstdint>
#include <dlfcn.h>

#define M_TOK 8192
#define KDIM  4096
#define NOUT  4096

// ---- arch-specific feature gate ----
#if (defined(__CUDA_ARCH_FEAT_SM103_ALL) || (defined(__CUDA_ARCH_SPECIFIC__) && (__CUDA_ARCH_SPECIFIC__ == 1030)))
#define HAS_TCGEN05 1
#else
#define HAS_TCGEN05 0
#endif

// ---- tcgen05 cg2 bf16 GEMM tiling (TMA pipeline) ----
#define CTBM 256                 // cluster tile M (128 per CTA)
#define CTBN 512                 // cluster tile N (2 dispatches of 256)
#define TKE  64                  // K elems per stage (128 B SW128 rows)
#define NKT  (KDIM / TKE)        // 64 k-tiles
#define STG  4
#define STAGE_BYTES (384 * 128)  // A 128 rows + B 2x128 rows, 128 B each = 48 KB
#define SMEM_DYN (2048 + STG * STAGE_BYTES)   // align slack + hdr + 192 KB
#define KB2 (KDIM * 2)

// ---- IMMA fallback tiling ----
#define IBM 128
#define IBN 128
#define IBK 64
#define IKT (KDIM / IBK)
#define ISTG 3

// ---------------- scratch ----------------
__device__ __align__(128) int8_t  g_qx8[(size_t)M_TOK * KDIM];
__device__ __align__(128) int8_t  g_qw8[(size_t)NOUT * KDIM];
__device__ __align__(128) uint16_t g_qx16[(size_t)M_TOK * KDIM];
__device__ __align__(128) uint16_t g_qw16[(size_t)NOUT * KDIM];
__device__ __align__(16) int8_t  g_b8[NOUT];
__device__ unsigned g_absmax_bits;

// ---------------- generic helpers ----------------
__device__ __forceinline__ unsigned pack4(int a, int b, int c, int d) {
    return (unsigned)(a & 0xff) | ((unsigned)(b & 0xff) << 8) |
           ((unsigned)(c & 0xff) << 16) | ((unsigned)(d & 0xff) << 24);
}
__device__ __forceinline__ unsigned bf16pair(int a, int b) {
    __nv_bfloat162 p;
    p.x = __float2bfloat16_rn((float)a);
    p.y = __float2bfloat16_rn((float)b);
    return *reinterpret_cast<unsigned*>(&p);
}
__device__ __forceinline__ void cp_async16(uint32_t dst, const void* src) {
    asm volatile("cp.async.cg.shared.global [%0], [%1], 16;" :: "r"(dst), "l"(src));
}
__device__ __forceinline__ void cp_commit() { asm volatile("cp.async.commit_group;"); }
template <int N> __device__ __forceinline__ void cp_wait() {
    asm volatile("cp.async.wait_group %0;" :: "n"(N));
}
__device__ __forceinline__ uint32_t smem_u32(const void* p) {
    uint32_t a;
    asm("{ .reg .u64 t; cvta.to.shared.u64 t, %1; cvt.u32.u64 %0, t; }" : "=r"(a) : "l"(p));
    return a;
}
__device__ __forceinline__ float requantf(float af, float bf, float alpha, float ys) {
    float v = rintf(af * alpha) + bf;
    v = fminf(fmaxf(v, -128.0f), 127.0f) * ys;
    return __half2float(__float2half_rn(v));
}

// deterministic per-block dtype consensus: 1=int32, 2=float32, 0=int8-native
__device__ __forceinline__ unsigned detect_mode(const unsigned* p, int mask, int mult) {
    int t = threadIdx.x;
    int i32ok = 1, f32ok = 1;
#pragma unroll
    for (int s = 0; s < 4; ++s) {
        int idx = ((t * 4 + s) * mult) & mask;
        unsigned w = p[idx];
        i32ok &= ((int)w == (int)(signed char)(w & 0xffu)) ? 1 : 0;
        float f = __uint_as_float(w);
        f32ok &= (f == rintf(f) && fabsf(f) <= 256.0f) ? 1 : 0;
    }
    int ni = __syncthreads_count(i32ok);
    int nf = __syncthreads_count(f32ok);
    return (ni == 256) ? 1u : ((nf == 256) ? 2u : 0u);
}

// ---------------- launch 0: repack (detect inline) + bias + absmax reset ----------------
__global__ void k_repack(const void* qw, const void* b) {
    unsigned mode = detect_mode((const unsigned*)qw, 4194304 - 1, 4099);
    if (blockIdx.x == 0 && threadIdx.x == 0) g_absmax_bits = 0u;
    unsigned* d8 = (unsigned*)g_qw8;
    uint2* d16 = (uint2*)g_qw16;
    int n4 = (NOUT * KDIM) / 4;
    int idx = blockIdx.x * blockDim.x + threadIdx.x;
    int stride = gridDim.x * blockDim.x;
    for (int i = idx; i < n4; i += stride) {
        int a, bq, c, d;
        if (mode == 1u) {
            int4 r = ((const int4*)qw)[i];
            a = r.x; bq = r.y; c = r.z; d = r.w;
        } else if (mode == 2u) {
            float4 r = ((const float4*)qw)[i];
            a = __float2int_rn(r.x); bq = __float2int_rn(r.y);
            c = __float2int_rn(r.z); d = __float2int_rn(r.w);
        } else {
            unsigned w = ((const unsigned*)qw)[i];
            a = (int)(signed char)(w); bq = (int)(signed char)(w >> 8);
            c = (int)(signed char)(w >> 16); d = (int)(signed char)(w >> 24);
        }
#if !HAS_TCGEN05
        d8[i] = pack4(a, bq, c, d);
#else
        (void)d8;
#endif
        uint2 o16; o16.x = bf16pair(a, bq); o16.y = bf16pair(c, d);
        d16[i] = o16;
    }
    if (blockIdx.x == 0) {
        unsigned bm = detect_mode((const unsigned*)b, 1024 - 1, 4);
        unsigned* bdst = (unsigned*)g_b8;
        for (int i = threadIdx.x; i < NOUT / 4; i += blockDim.x) {
            unsigned o;
            if (bm == 1u) {
                int4 r = ((const int4*)b)[i];
                o = pack4(r.x, r.y, r.z, r.w);
            } else if (bm == 2u) {
                float4 r = ((const float4*)b)[i];
                o = pack4(__float2int_rn(r.x), __float2int_rn(r.y),
                          __float2int_rn(r.z), __float2int_rn(r.w));
            } else {
                o = ((const unsigned*)b)[i];
            }
            bdst[i] = o;
        }
    }
}

// ---------------- launch 1: absmax over f32 x ----------------
__global__ void k_absmax(const uint4* __restrict__ xv, int n4) {
    unsigned m = 0u;
    int idx = blockIdx.x * blockDim.x + threadIdx.x;
    int stride = gridDim.x * blockDim.x;
    for (int i = idx; i < n4; i += stride) {
        uint4 v = xv[i];
        m = max(m, v.x & 0x7fffffffu);
        m = max(m, v.y & 0x7fffffffu);
        m = max(m, v.z & 0x7fffffffu);
        m = max(m, v.w & 0x7fffffffu);
    }
#pragma unroll
    for (int o = 16; o; o >>= 1) m = max(m, __shfl_xor_sync(0xffffffffu, m, o));
    __shared__ unsigned sm[32];
    int lane = threadIdx.x & 31, wid = threadIdx.x >> 5;
    if (lane == 0) sm[wid] = m;
    __syncthreads();
    if (wid == 0) {
        unsigned v = (lane < (int)(blockDim.x >> 5)) ? sm[lane] : 0u;
#pragma unroll
        for (int o = 16; o; o >>= 1) v = max(v, __shfl_xor_sync(0xffffffffu, v, o));
        if (lane == 0) atomicMax(&g_absmax_bits, v);
    }
}

// ---------------- launch 2: quantize f32 x -> bf16 (+int8 only on fallback) ----------------
__device__ __forceinline__ int quant1(float f, float s, float r) {
    float q0 = f * r;
    float e  = fmaf(-s, q0, f);
    float q  = fmaf(r, e, q0);
    float qf = rintf(q);
    qf = fminf(fmaxf(qf, -128.0f), 127.0f);
    return (int)qf;
}

__global__ void k_quant(const float4* __restrict__ xv, int n4) {
    float amax = __uint_as_float(g_absmax_bits);
    float s = __fdiv_rn(amax, 127.0f);
    float r = __frcp_rn(s);
    int idx = blockIdx.x * blockDim.x + threadIdx.x;
    int stride = gridDim.x * blockDim.x;
    unsigned* q8 = reinterpret_cast<unsigned*>(g_qx8);
    uint2* q16 = reinterpret_cast<uint2*>(g_qx16);
    for (int i = idx; i < n4; i += stride) {
        float4 v = xv[i];
        int a = quant1(v.x, s, r), b = quant1(v.y, s, r);
        int c = quant1(v.z, s, r), d = quant1(v.w, s, r);
#if !HAS_TCGEN05
        q8[i] = pack4(a, b, c, d);
#else
        (void)q8;
#endif
        uint2 o16; o16.x = bf16pair(a, b); o16.y = bf16pair(c, d);
        q16[i] = o16;
    }
}

// ================= tcgen05 cg2 bf16 GEMM, TMA pipeline (launch 3) =================
#if HAS_TCGEN05
__device__ __forceinline__ uint32_t elect_one() {
    uint32_t p;
    asm volatile("{\n\t.reg .pred q;\n\telect.sync _|q, 0xFFFFFFFF;\n\tselp.b32 %0, 1, 0, q;\n\t}" : "=r"(p));
    return p;
}
#define MBAR_INIT(a, c) asm volatile("mbarrier.init.shared.b64 [%0], %1;" :: "r"(a), "r"(c) : "memory")
#define MBAR_WAIT(a, ph) do { \
    uint32_t _m = (a), _p = (ph), _d; \
    asm volatile("{\n\t.reg .pred p;\n\tmbarrier.try_wait.parity.acquire.cta.shared::cta.b64 p, [%1], %2;\n\tselp.b32 %0, 1, 0, p;\n\t}" \
                 : "=r"(_d) : "r"(_m), "r"(_p) : "memory"); \
    if (!_d) { \
        asm volatile("{\n\t.reg .pred P;\n\tWL_%=:\n\tmbarrier.try_wait.parity.acquire.cta.shared::cta.b64 P, [%0], %1, 0x989680;\n\t@P bra.uni WD_%=;\n\tbra.uni WL_%=;\n\tWD_%=:\n\t}" \
                     :: "r"(_m), "r"(_p) : "memory"); \
    } } while (0)
#define MBAR_ARRIVE_RANK0(addr) \
    asm volatile("{\n\t.reg .b32 ra;\n\tmapa.shared::cluster.u32 ra, %0, %1;\n\t" \
                 "mbarrier.arrive.shared::cluster.b64 _, [ra];\n\t}" \
                 :: "r"(addr), "r"(0) : "memory")
#define MBAR_EXPECT_TX(addr, tx) \
    asm volatile("mbarrier.arrive.expect_tx.shared.b64 _, [%0], %1;" :: "r"(addr), "r"(tx) : "memory")
#define TMA_LOAD(smem, map, x, y, mbar) \
    asm volatile("cp.async.bulk.tensor.3d.shared::cta.global.tile.mbarrier::complete_tx::bytes " \
                 "[%0], [%1, {%2, %3, %4}], [%5];" \
                 :: "r"(smem), "l"(map), "r"(x), "r"(y), "r"(0), "r"(mbar) : "memory")
#define TC_ALLOC_CG2(sm, n)  asm volatile("tcgen05.alloc.cta_group::2.sync.aligned.shared::cta.b32 [%0], %1;" :: "r"(sm), "r"(n) : "memory")
#define TC_RELINQ_CG2()      asm volatile("tcgen05.relinquish_alloc_permit.cta_group::2.sync.aligned;")
#define TC_DEALLOC_CG2(t, n) asm volatile("tcgen05.dealloc.cta_group::2.sync.aligned.b32 %0, %1;" :: "r"(t), "r"(n))
#define TC_COMMIT_MC2(mb)    asm volatile("tcgen05.commit.cta_group::2.mbarrier::arrive::one.shared::cluster.multicast::cluster.b64 [%0], %1;" :: "r"(mb), "h"((uint16_t)3) : "memory")
#define TC_FENCE_AFTER()     asm volatile("tcgen05.fence::after_thread_sync;" ::: "memory")
#define TC_WAIT_LD()         asm volatile("tcgen05.wait::ld.sync.aligned;" ::: "memory")
#define CLUSTER_SYNC() do { \
    asm volatile("barrier.cluster.arrive.aligned;" ::: "memory"); \
    asm volatile("barrier.cluster.wait.aligned;" ::: "memory"); } while (0)
#define TC_LD_X32(r, a) \
    asm volatile("tcgen05.ld.sync.aligned.32x32b.x32.b32 " \
        "{%0,%1,%2,%3,%4,%5,%6,%7,%8,%9,%10,%11,%12,%13,%14,%15," \
        "%16,%17,%18,%19,%20,%21,%22,%23,%24,%25,%26,%27,%28,%29,%30,%31}, [%32];" \
        : "=r"((r)[0]),"=r"((r)[1]),"=r"((r)[2]),"=r"((r)[3]),"=r"((r)[4]),"=r"((r)[5]),"=r"((r)[6]),"=r"((r)[7]), \
          "=r"((r)[8]),"=r"((r)[9]),"=r"((r)[10]),"=r"((r)[11]),"=r"((r)[12]),"=r"((r)[13]),"=r"((r)[14]),"=r"((r)[15]), \
          "=r"((r)[16]),"=r"((r)[17]),"=r"((r)[18]),"=r"((r)[19]),"=r"((r)[20]),"=r"((r)[21]),"=r"((r)[22]),"=r"((r)[23]), \
          "=r"((r)[24]),"=r"((r)[25]),"=r"((r)[26]),"=r"((r)[27]),"=r"((r)[28]),"=r"((r)[29]),"=r"((r)[30]),"=r"((r)[31]) \
        : "r"(a))

// SW128 K-major smem descriptor: layout=2, version=1, SBO=64, LBO=1
static __device__ __forceinline__ uint64_t make_desc(uint32_t addr) {
    return ((uint64_t)2 << 61) | ((uint64_t)1 << 46) | ((uint64_t)64 << 32) |
           ((uint64_t)1 << 16) | ((uint64_t)(addr >> 4) & 0x3FFF);
}
__device__ __forceinline__ void tc_mma_bf16_cg2(uint32_t d, uint64_t a, uint64_t b, uint32_t idesc, uint32_t acc) {
    asm volatile(
        "{\n\t.reg .pred p;\n\tsetp.ne.u32 p, %5, 0;\n\t"
        "tcgen05.mma.cta_group::2.kind::f16 [%0], %1, %2, %3, {%4,%4,%4,%4,%4,%4,%4,%4}, p;\n\t}"
        :: "r"(d), "l"(a), "l"(b), "r"(idesc), "r"(0u), "r"(acc) : "memory");
}
// dtype=F32(1)<<4 | atype=BF16(1)<<7 | btype=BF16(1)<<10 | (N/8)<<17 | (M_TOTAL/16)<<24
#define IDESC_CG2 ((1u << 4) | (1u << 7) | (1u << 10) | ((256u / 8) << 17) | ((256u / 16) << 24))
#endif  // HAS_TCGEN05

// Barrier offsets within header (relative to aligned sb):
//   tmem ptr @0; full_local[s] @8+8s; fullc[s] @40+8s (rank0, count 2);
//   empty[s] @72+8s; final @104
__global__ __launch_bounds__(256, 1) __cluster_dims__(2, 1, 1)
void k_gemm_tc(const __grid_constant__ CUtensorMap tma_a,
               const __grid_constant__ CUtensorMap tma_b,
               const float* __restrict__ s0_p, const float* __restrict__ s1_p,
               float* __restrict__ out)
{
#if HAS_TCGEN05
    extern __shared__ __align__(16) uint8_t dsm[];
    const uint32_t sb = (smem_u32(dsm) + 1023u) & ~1023u;
    const int tid = threadIdx.x, wid = tid >> 5, lane = tid & 31;
    uint32_t rank;
    asm("mov.u32 %0, %%cluster_ctarank;" : "=r"(rank));
    const int tile_n = blockIdx.x >> 1, tile_m = blockIdx.y;

    if (tid == 0) {
#pragma unroll
        for (int s = 0; s < STG; ++s) {
            MBAR_INIT(sb + 8 + s * 8, 1);    // full_local: tx-completed
            MBAR_INIT(sb + 40 + s * 8, 2);   // fullc: one relay arrival per CTA
            MBAR_INIT(sb + 72 + s * 8, 1);   // empty: commit multicast
        }
        MBAR_INIT(sb + 104, 1);              // final
    }
    if (wid == 0) TC_ALLOC_CG2(sb, 512);
    __syncthreads();
    uint32_t tmem;
    asm volatile("ld.shared.b32 %0, [%1];" : "=r"(tmem) : "r"(sb));
    CLUSTER_SYNC();   // all barriers live cluster-wide before use

    const int a_row = tile_m * CTBM + (int)rank * 128;
    const int b_row0 = tile_n * CTBN + (int)rank * 128;        // half d=0
    const int b_row1 = tile_n * CTBN + 256 + (int)rank * 128;  // half d=1

    // ---------------- producer: one thread per CTA ----------------
    if (tid == 32) {
        int phe[STG] = {0, 0, 0, 0};
        for (int kt = 0; kt < NKT; ++kt) {
            int s = kt & (STG - 1);
            if (kt >= STG) { MBAR_WAIT(sb + 72 + s * 8, phe[s]); phe[s] ^= 1; }
            uint32_t stg = sb + 1024 + s * STAGE_BYTES;
            uint32_t mb = sb + 8 + s * 8;
            MBAR_EXPECT_TX(mb, STAGE_BYTES);
            TMA_LOAD(stg,         &tma_a, kt * TKE, a_row,  mb);
            TMA_LOAD(stg + 16384, &tma_b, kt * TKE, b_row0, mb);
            TMA_LOAD(stg + 32768, &tma_b, kt * TKE, b_row1, mb);
        }
    }
    // ---------------- relay: one thread per CTA ----------------
    else if (tid == 64) {
        int phl[STG] = {0, 0, 0, 0};
        for (int kt = 0; kt < NKT; ++kt) {
            int s = kt & (STG - 1);
            MBAR_WAIT(sb + 8 + s * 8, phl[s]);  // local 48 KB landed
            phl[s] ^= 1;
            MBAR_ARRIVE_RANK0(sb + 40 + s * 8); // report to leader
        }
    }
    // ---------------- consumer: one thread, rank0 only ----------------
    else if (tid == 0 && rank == 0) {
        int phf[STG] = {0, 0, 0, 0};
        for (int kt = 0; kt < NKT; ++kt) {
            int s = kt & (STG - 1);
            MBAR_WAIT(sb + 40 + s * 8, phf[s]); // both CTAs' stage s resident
            phf[s] ^= 1;
            uint32_t stg = sb + 1024 + s * STAGE_BYTES;
            uint64_t ad = make_desc(stg);
            uint64_t b0 = make_desc(stg + 16384);
            uint64_t b1 = make_desc(stg + 32768);
#pragma unroll
            for (int c = 0; c < 4; ++c) {       // 4 k-steps of K=16 (32 B = +2 units)
                uint32_t acc = (kt > 0 || c > 0) ? 1u : 0u;
                tc_mma_bf16_cg2(tmem,       ad + c * 2, b0 + c * 2, IDESC_CG2, acc);
                tc_mma_bf16_cg2(tmem + 256, ad + c * 2, b1 + c * 2, IDESC_CG2, acc);
            }
            TC_COMMIT_MC2((kt == NKT - 1) ? (sb + 104) : (sb + 72 + s * 8));
        }
    }

    // ---------------- epilogue: all threads ----------------
    MBAR_WAIT(sb + 104, 0);
    TC_FENCE_AFTER();

    const float v0 = *s0_p, v1 = *s1_p;
    const float ys    = fmaxf(v0, v1);
    const float alpha = fminf(v0, v1);
    const int chalf = wid >> 2, wsub = wid & 3;
    const uint32_t tb = tmem + chalf * 256 + ((uint32_t)wsub << 21);
    const int mrow = tile_m * CTBM + (int)rank * 128 + wsub * 32 + lane;
    const int cbase = tile_n * CTBN + chalf * 256;
    float* orow = out + (size_t)mrow * NOUT + cbase;

#pragma unroll
    for (int cc = 0; cc < 8; ++cc) {
        uint32_t r[32];
        TC_LD_X32(r, tb + cc * 32);
        TC_WAIT_LD();
        float4 o4;
#pragma unroll
        for (int j = 0; j < 32; j += 4) {
            int col = cc * 32 + j;
            o4.x = requantf(__uint_as_float(r[j]),     (float)g_b8[cbase + col],     alpha, ys);
            o4.y = requantf(__uint_as_float(r[j + 1]), (float)g_b8[cbase + col + 1], alpha, ys);
            o4.z = requantf(__uint_as_float(r[j + 2]), (float)g_b8[cbase + col + 2], alpha, ys);
            o4.w = requantf(__uint_as_float(r[j + 3]), (float)g_b8[cbase + col + 3], alpha, ys);
            *reinterpret_cast<float4*>(orow + col) = o4;
        }
    }

    __syncthreads();
    if (wid == 0) {
        TC_RELINQ_CG2();
        TC_DEALLOC_CG2(tmem, 512);
    }
    CLUSTER_SYNC();
#endif  // HAS_TCGEN05
}

// ================= IMMA fallback GEMM (launch 4; compile-time no-op when tc) =================
__device__ __forceinline__ int iswz(int row, int c) {
    return row * 64 + ((c ^ ((row >> 1) & 3)) << 4);
}
__device__ __forceinline__ void ldsm_x4(uint32_t& r0, uint32_t& r1, uint32_t& r2, uint32_t& r3, uint32_t addr) {
    asm volatile("ldmatrix.sync.aligned.m8n8.x4.shared.b16 {%0,%1,%2,%3}, [%4];"
                 : "=r"(r0), "=r"(r1), "=r"(r2), "=r"(r3) : "r"(addr));
}
__device__ __forceinline__ void mma_s8(int* c, const uint32_t* a, const uint32_t* b) {
    asm volatile(
        "mma.sync.aligned.m16n8k32.row.col.s32.s8.s8.s32 "
        "{%0,%1,%2,%3}, {%4,%5,%6,%7}, {%8,%9}, {%0,%1,%2,%3};"
        : "+r"(c[0]), "+r"(c[1]), "+r"(c[2]), "+r"(c[3])
        : "r"(a[0]), "r"(a[1]), "r"(a[2]), "r"(a[3]), "r"(b[0]), "r"(b[1]));
}

__global__ __launch_bounds__(256) void k_gemm_imma(
    const float* __restrict__ s0_p, const float* __restrict__ s1_p,
    float* __restrict__ out)
{
#if !HAS_TCGEN05
    __shared__ __align__(16) int8_t sA[ISTG][IBM * IBK];
    __shared__ __align__(16) int8_t sB[ISTG][IBN * IBK];

    const int tid  = threadIdx.x;
    const int lane = tid & 31, warp = tid >> 5;
    const int wm = warp & 1;
    const int wn = warp >> 1;
    const int bm = blockIdx.y * IBM, bn = blockIdx.x * IBN;

    const uint32_t sAu = (uint32_t)__cvta_generic_to_shared(&sA[0][0]);
    const uint32_t sBu = (uint32_t)__cvta_generic_to_shared(&sB[0][0]);

    const int8_t* Ag = g_qx8 + (size_t)bm * KDIM;
    const int8_t* Bg = g_qw8 + (size_t)bn * KDIM;

    const int r0 = tid >> 2, c0 = tid & 3;
    const int r1 = r0 + 64;

    const int rowA_base = wm * 64 + (lane & 7) + ((lane >> 3) & 1) * 8;
    const int cA_off    = lane >> 4;
    const int rowB_base = wn * 32 + (lane & 7) + ((lane >> 4) << 3);
    const int cB_off    = (lane >> 3) & 1;

    int acc[4][4][4];
#pragma unroll
    for (int i = 0; i < 4; i++)
#pragma unroll
        for (int j = 0; j < 4; j++)
#pragma unroll
            for (int q = 0; q < 4; q++) acc[i][j][q] = 0;

    auto load_stage = [&](int st, int kt) {
        uint32_t sa = sAu + st * (IBM * IBK);
        uint32_t sb = sBu + st * (IBN * IBK);
        const int8_t* ab = Ag + kt * IBK;
        const int8_t* bb = Bg + kt * IBK;
        cp_async16(sa + iswz(r0, c0), ab + (size_t)r0 * KDIM + c0 * 16);
        cp_async16(sa + iswz(r1, c0), ab + (size_t)r1 * KDIM + c0 * 16);
        cp_async16(sb + iswz(r0, c0), bb + (size_t)r0 * KDIM + c0 * 16);
        cp_async16(sb + iswz(r1, c0), bb + (size_t)r1 * KDIM + c0 * 16);
    };

    auto compute_stage = [&](int st) {
        uint32_t sa = sAu + st * (IBM * IBK);
        uint32_t sb = sBu + st * (IBN * IBK);
#pragma unroll
        for (int kk = 0; kk < 2; ++kk) {
            uint32_t a[4][4];
#pragma unroll
            for (int mf = 0; mf < 4; ++mf) {
                int row = rowA_base + mf * 16;
                int c   = 2 * kk + cA_off;
                ldsm_x4(a[mf][0], a[mf][1], a[mf][2], a[mf][3], sa + iswz(row, c));
            }
            uint32_t b[4][2];
#pragma unroll
            for (int nf2 = 0; nf2 < 2; ++nf2) {
                int row = rowB_base + nf2 * 16;
                int c   = 2 * kk + cB_off;
                uint32_t t0, t1, t2, t3;
                ldsm_x4(t0, t1, t2, t3, sb + iswz(row, c));
                b[2 * nf2][0] = t0; b[2 * nf2][1] = t1;
                b[2 * nf2 + 1][0] = t2; b[2 * nf2 + 1][1] = t3;
            }
#pragma unroll
            for (int mf = 0; mf < 4; ++mf)
#pragma unroll
                for (int nf = 0; nf < 4; ++nf)
                    mma_s8(acc[mf][nf], a[mf], b[nf]);
        }
    };

    load_stage(0, 0); cp_commit();
    load_stage(1, 1); cp_commit();

    for (int kt = 0; kt < IKT; ++kt) {
        cp_wait<1>();
        __syncthreads();
        if (kt + 2 < IKT) load_stage((kt + 2) % ISTG, kt + 2);
        cp_commit();
        compute_stage(kt % ISTG);
    }

    const float v0 = *s0_p, v1 = *s1_p;
    const float ys    = fmaxf(v0, v1);
    const float alpha = fminf(v0, v1);
    const int grp = lane >> 2, qd = lane & 3;
#pragma unroll
    for (int mf = 0; mf < 4; ++mf) {
#pragma unroll
        for (int nf = 0; nf < 4; ++nf) {
            int row = bm + wm * 64 + mf * 16 + grp;
            int col = bn + wn * 32 + nf * 8 + 2 * qd;
            float b0f = (float)g_b8[col];
            float b1f = (float)g_b8[col + 1];
            float2 h0, h1;
            h0.x = requantf(__int2float_rn(acc[mf][nf][0]), b0f, alpha, ys);
            h0.y = requantf(__int2float_rn(acc[mf][nf][1]), b1f, alpha, ys);
            h1.x = requantf(__int2float_rn(acc[mf][nf][2]), b0f, alpha, ys);
            h1.y = requantf(__int2float_rn(acc[mf][nf][3]), b1f, alpha, ys);
            *reinterpret_cast<float2*>(out + (size_t)row * NOUT + col) = h0;
            *reinterpret_cast<float2*>(out + (size_t)(row + 8) * NOUT + col) = h1;
        }
    }
#endif  // !HAS_TCGEN05
}

// ---------------- host: tensor map encoding via dlopen (no -lcuda link dep) ----------------
typedef CUresult (*pfn_encode_t)(CUtensorMap*, CUtensorMapDataType, cuuint32_t, void*,
                                 const cuuint64_t*, const cuuint64_t*, const cuuint32_t*,
                                 const cuuint32_t*, CUtensorMapInterleave, CUtensorMapSwizzle,
                                 CUtensorMapL2promotion, CUtensorMapFloatOOBfill);

static void encode_map(pfn_encode_t enc, CUtensorMap* m, void* base,
                       uint64_t d0, uint64_t d1) {
    cuuint64_t dims[3]    = {d0, d1, 1};
    cuuint64_t strides[2] = {d0 * 2, d0 * d1 * 2};
    cuuint32_t box[3]     = {64, 128, 1};
    cuuint32_t es[3]      = {1, 1, 1};
    enc(m, CU_TENSOR_MAP_DATA_TYPE_BFLOAT16, 3, base, dims, strides, box, es,
        CU_TENSOR_MAP_INTERLEAVE_NONE, CU_TENSOR_MAP_SWIZZLE_128B,
        CU_TENSOR_MAP_L2_PROMOTION_L2_128B, CU_TENSOR_MAP_FLOAT_OOB_FILL_NONE);
}

// ---------------- launch: bind inputs by SIZE (permutation-proof) ----------------
extern "C" void kernel_launch(void* const* d_in, const int* in_sizes, int n_in,
                              void* d_out, int out_size) {
    const void* x  = nullptr;
    const void* qw = nullptr;
    const void* bi = nullptr;
    const float* sc[2] = {nullptr, nullptr};
    int nsc = 0;
    for (int i = 0; i < n_in; ++i) {
        int sz = in_sizes[i];
        if      (sz == M_TOK * KDIM) x  = d_in[i];
        else if (sz == NOUT * KDIM)  qw = d_in[i];
        else if (sz == NOUT)         bi = d_in[i];
        else if (sz == 1 && nsc < 2) sc[nsc++] = (const float*)d_in[i];
    }
    float* out = (float*)d_out;

    cudaFuncSetAttribute(k_gemm_tc, cudaFuncAttributeMaxDynamicSharedMemorySize, SMEM_DYN);

    // Build TMA descriptors (cheap host work, done every call — deterministic)
    alignas(64) CUtensorMap ta, tb;
    memset(&ta, 0, sizeof(ta));
    memset(&tb, 0, sizeof(tb));
    void* drv = dlopen("libcuda.so.1", RTLD_LAZY);
    if (!drv) drv = dlopen("libcuda.so", RTLD_LAZY);
    pfn_encode_t enc = drv ? (pfn_encode_t)dlsym(drv, "cuTensorMapEncodeTiled") : nullptr;
    if (enc) {
        void *pa = nullptr, *pb = nullptr;
        cudaGetSymbolAddress(&pa, g_qx16);
        cudaGetSymbolAddress(&pb, g_qw16);
        encode_map(enc, &ta, pa, KDIM, M_TOK);
        encode_map(enc, &tb, pb, KDIM, NOUT);
    }

    const int n4 = (M_TOK * KDIM) / 4;

    k_repack<<<4096, 256>>>(qw, bi);                      // launch 0 (detect inline)
    k_absmax<<<1184, 256>>>((const uint4*)x, n4);         // launch 1
    k_quant<<<1184, 256>>>((const float4*)x, n4);         // launch 2

    dim3 gt((NOUT / CTBN) * 2, M_TOK / CTBM);             // (16, 32), clusters of 2 on x
    k_gemm_tc<<<gt, 256, SMEM_DYN>>>(ta, tb, sc[0], sc[1], out);  // launch 3 <- ncu slot

    dim3 gi(NOUT / IBN, M_TOK / IBM);                     // (32, 64)
    k_gemm_imma<<<gi, 256>>>(sc[0], sc[1], out);          // launch 4 (no-op when tc)
}